// round 2
// baseline (speedup 1.0000x reference)
#include <cuda_runtime.h>

#define N_NODES_MAX 50000
#define N_EDGES_MAX 800000
#define NFEAT 128
#define HID 256
#define BN_EPS 1e-5f

// ---------------- scratch (static __device__, no allocation) ----------------
__device__ float  g_h  [(size_t)N_NODES_MAX * HID];  // h' = (A@W) * dis[row]
__device__ float  g_acc[(size_t)N_NODES_MAX * HID];  // edge-accumulator
__device__ float  g_y  [(size_t)N_NODES_MAX * HID];  // post-aggregation activations
__device__ float  g_dis[N_NODES_MAX];
__device__ int    g_deg[N_NODES_MAX];
__device__ int    g_src[N_EDGES_MAX];
__device__ int    g_dst[N_EDGES_MAX];
__device__ int    g_is32;
__device__ double g_sum[HID];
__device__ double g_sumsq[HID];
__device__ float  g_bns[HID];   // BN scale  (gamma * rsqrt(var+eps))
__device__ float  g_bnt[HID];   // BN shift  (beta - mean*scale)

// ---------------- edge-index dtype probe + decode ----------------
__global__ void init_kernel(int n) {
    int i = blockIdx.x * blockDim.x + threadIdx.x;
    if (i < n) g_deg[i] = 0;
    if (i == 0) g_is32 = 0;
    if (i < HID) { g_sum[i] = 0.0; g_sumsq[i] = 0.0; }
}

// Scan first E 64-bit words (safe for both int32[2E] and int64[2E] buffers).
// Genuine int64 indices are all < M; packed int32 pairs mostly exceed 2^32.
__global__ void detect_kernel(const unsigned long long* __restrict__ p,
                              int E, int M) {
    int i = blockIdx.x * blockDim.x + threadIdx.x;
    if (i < E && p[i] >= (unsigned long long)M) g_is32 = 1;
}

__global__ void convert_kernel(const void* __restrict__ ei, int E) {
    int e = blockIdx.x * blockDim.x + threadIdx.x;
    if (e >= E) return;
    int s, d;
    if (g_is32) {
        const int* p = (const int*)ei;
        s = p[e]; d = p[E + e];
    } else {
        const long long* p = (const long long*)ei;
        s = (int)p[e]; d = (int)p[(size_t)E + e];
    }
    g_src[e] = s;
    g_dst[e] = d;
    atomicAdd(&g_deg[d], 1);
}

__global__ void dis_kernel(int n) {
    int i = blockIdx.x * blockDim.x + threadIdx.x;
    if (i < n) g_dis[i] = rsqrtf((float)(g_deg[i] + 1));  // +1 = self loop
}

// ---------------- GEMM: C[M,256] = op(A)[M,K] @ W[K,256] ----------------
// op(A): optional per-K-column affine (BN folded into the load of A).
// Epilogue: optional *dis[row]; optional +bias[col]; optional zero of acc buf.
template<int K, bool AFFINE, bool SCALE_ROW, bool ZERO_ACC, bool ADD_BIAS>
__global__ void __launch_bounds__(256)
gemm_kernel(const float* __restrict__ A, const float* __restrict__ W,
            float* __restrict__ C, float* __restrict__ Z, int M,
            const float* __restrict__ bias)
{
    __shared__ float As[16][68];   // [k][row], padded
    __shared__ float Bs[16][64];   // [k][col]

    const int tid = threadIdx.x;
    const int rowBase = blockIdx.x * 64;
    const int colBase = blockIdx.y * 64;
    const int tx = tid & 15;       // output col group
    const int ty = tid >> 4;       // output row group

    const int ar = tid >> 2;           // 0..63  (A tile row)
    const int ac = (tid & 3) * 4;      // 0,4,8,12 (A tile col base)
    const int br = tid >> 4;           // 0..15  (B tile row)
    const int bc = (tid & 15) * 4;     // 0..60  (B tile col base)

    const bool aValid = (rowBase + ar) < M;
    const float* Aptr = A + (size_t)(rowBase + ar) * K + ac;

    float acc[4][4] = {};

    for (int kt = 0; kt < K; kt += 16) {
        float4 av = make_float4(0.f, 0.f, 0.f, 0.f);
        if (aValid) av = *(const float4*)(Aptr + kt);
        if (AFFINE) {
            float4 s = *(const float4*)(g_bns + kt + ac);
            float4 t = *(const float4*)(g_bnt + kt + ac);
            av.x = fmaf(av.x, s.x, t.x);
            av.y = fmaf(av.y, s.y, t.y);
            av.z = fmaf(av.z, s.z, t.z);
            av.w = fmaf(av.w, s.w, t.w);
        }
        As[ac + 0][ar] = av.x;
        As[ac + 1][ar] = av.y;
        As[ac + 2][ar] = av.z;
        As[ac + 3][ar] = av.w;

        float4 bv = *(const float4*)(W + (size_t)(kt + br) * HID + colBase + bc);
        *(float4*)&Bs[br][bc] = bv;

        __syncthreads();
        #pragma unroll
        for (int k = 0; k < 16; k++) {
            float a0[4], b0[4];
            #pragma unroll
            for (int i = 0; i < 4; i++) a0[i] = As[k][ty * 4 + i];
            #pragma unroll
            for (int j = 0; j < 4; j++) b0[j] = Bs[k][tx * 4 + j];
            #pragma unroll
            for (int i = 0; i < 4; i++)
                #pragma unroll
                for (int j = 0; j < 4; j++)
                    acc[i][j] = fmaf(a0[i], b0[j], acc[i][j]);
        }
        __syncthreads();
    }

    #pragma unroll
    for (int i = 0; i < 4; i++) {
        int grow = rowBase + ty * 4 + i;
        if (grow >= M) continue;
        float d = SCALE_ROW ? g_dis[grow] : 1.f;
        #pragma unroll
        for (int j = 0; j < 4; j++) {
            int gcol = colBase + tx * 4 + j;
            float v = acc[i][j];
            if (SCALE_ROW) v *= d;
            if (ADD_BIAS)  v += bias[gcol];
            size_t idx = (size_t)grow * HID + gcol;
            C[idx] = v;
            if (ZERO_ACC) Z[idx] = 0.f;
        }
    }
}

// ---------------- edge scatter: acc[dst] += h'[src] ----------------
// One warp per edge; each lane handles 2 float4 (8 floats) of the 256.
__global__ void __launch_bounds__(256)
edge_scatter(const float* __restrict__ h, float* __restrict__ acc, int E)
{
    int gt = blockIdx.x * blockDim.x + threadIdx.x;
    int e = gt >> 5;
    int lane = gt & 31;
    if (e >= E) return;
    int s = __ldg(g_src + e);
    int d = __ldg(g_dst + e);
    const float4* hs = (const float4*)(h + (size_t)s * HID);
    float* ad = acc + (size_t)d * HID;
    float4 v0 = __ldg(hs + lane);
    float4 v1 = __ldg(hs + lane + 32);
    int c0 = lane * 4, c1 = 128 + lane * 4;
    atomicAdd(ad + c0 + 0, v0.x); atomicAdd(ad + c0 + 1, v0.y);
    atomicAdd(ad + c0 + 2, v0.z); atomicAdd(ad + c0 + 3, v0.w);
    atomicAdd(ad + c1 + 0, v1.x); atomicAdd(ad + c1 + 1, v1.y);
    atomicAdd(ad + c1 + 2, v1.z); atomicAdd(ad + c1 + 3, v1.w);
}

// ---------------- combine + BN statistics ----------------
// y = dis[row] * (h' + acc); column sums / sum-squares in double.
#define STAT_RPB 128
__global__ void __launch_bounds__(HID)
stats_kernel(const float* __restrict__ h, const float* __restrict__ acc,
             float* __restrict__ y, int M)
{
    int col = threadIdx.x;
    int r0 = blockIdx.x * STAT_RPB;
    int r1 = min(r0 + STAT_RPB, M);
    double ds = 0.0, dsq = 0.0;
    for (int r = r0; r < r1; r++) {
        float di = g_dis[r];
        size_t idx = (size_t)r * HID + col;
        float v = di * (h[idx] + acc[idx]);
        y[idx] = v;
        ds += v;
        dsq += (double)v * (double)v;
    }
    atomicAdd(&g_sum[col], ds);
    atomicAdd(&g_sumsq[col], dsq);
}

// ---------------- BN finalize: fold (mean,var,gamma,beta) into affine ------
// Note: pre-BN bias (b1/b2) cancels under BN mean subtraction, so omitted.
__global__ void bn_finalize(const float* __restrict__ gamma,
                            const float* __restrict__ beta, int M)
{
    int c = threadIdx.x;
    double m   = g_sum[c] / (double)M;
    double var = g_sumsq[c] / (double)M - m * m;
    float sc = gamma[c] * rsqrtf((float)var + BN_EPS);
    g_bns[c] = sc;
    g_bnt[c] = beta[c] - (float)m * sc;
    g_sum[c] = 0.0; g_sumsq[c] = 0.0;   // ready for next layer's stats
}

// ---------------- launch ----------------
extern "C" void kernel_launch(void* const* d_in, const int* in_sizes, int n_in,
                              void* d_out, int out_size)
{
    const float* x   = (const float*)d_in[0];
    const void*  ei  = d_in[1];
    const float* W1  = (const float*)d_in[2];
    // d_in[3] = b1 (cancels in BN)
    const float* g1  = (const float*)d_in[4];
    const float* be1 = (const float*)d_in[5];
    const float* W2  = (const float*)d_in[6];
    // d_in[7] = b2 (cancels in BN)
    const float* g2  = (const float*)d_in[8];
    const float* be2 = (const float*)d_in[9];
    const float* Wfc = (const float*)d_in[10];
    const float* bfc = (const float*)d_in[11];
    float* out = (float*)d_out;

    const int M = in_sizes[0] / NFEAT;   // 50000
    const int E = in_sizes[1] / 2;       // 800000

    void *p_h, *p_acc, *p_y;
    cudaGetSymbolAddress(&p_h,   g_h);
    cudaGetSymbolAddress(&p_acc, g_acc);
    cudaGetSymbolAddress(&p_y,   g_y);
    float* h   = (float*)p_h;
    float* acc = (float*)p_acc;
    float* y   = (float*)p_y;

    const int TB = 256;
    dim3 gemmGrid((M + 63) / 64, HID / 64);
    long long edgeThreads = (long long)E * 32;
    int edgeBlocks  = (int)((edgeThreads + TB - 1) / TB);
    int statsBlocks = (M + STAT_RPB - 1) / STAT_RPB;

    // edge decode (dtype-robust) + degrees + normalization coefficients
    init_kernel<<<(M + TB - 1) / TB, TB>>>(M);
    detect_kernel<<<(E + TB - 1) / TB, TB>>>((const unsigned long long*)ei, E, M);
    convert_kernel<<<(E + TB - 1) / TB, TB>>>(ei, E);
    dis_kernel<<<(M + TB - 1) / TB, TB>>>(M);

    // ---- layer 1: GCNConv(x, W1) + BN1 (folded) ----
    gemm_kernel<NFEAT, false, true, true, false>
        <<<gemmGrid, TB>>>(x, W1, h, acc, M, nullptr);
    edge_scatter<<<edgeBlocks, TB>>>(h, acc, E);
    stats_kernel<<<statsBlocks, HID>>>(h, acc, y, M);
    bn_finalize<<<1, HID>>>(g1, be1, M);

    // ---- layer 2: GCNConv(bn1(y), W2) + BN2 (folded) ----
    gemm_kernel<HID, true, true, true, false>
        <<<gemmGrid, TB>>>(y, W2, h, acc, M, nullptr);
    edge_scatter<<<edgeBlocks, TB>>>(h, acc, E);
    stats_kernel<<<statsBlocks, HID>>>(h, acc, y, M);
    bn_finalize<<<1, HID>>>(g2, be2, M);

    // ---- FC: out = bn2(y) @ Wfc + bfc ----
    gemm_kernel<HID, true, false, false, true>
        <<<gemmGrid, TB>>>(y, Wfc, out, nullptr, M, bfc);
}

// round 3
// speedup vs baseline: 2.2675x; 2.2675x over previous
#include <cuda_runtime.h>

#define N_NODES_MAX 50000
#define N_EDGES_MAX 800000
#define NFEAT 128
#define HID 256
#define BN_EPS 1e-5f

// ---------------- scratch (static __device__, no allocation) ----------------
__device__ float  g_h  [(size_t)N_NODES_MAX * HID];  // h' = (opA@W) * dis[row]
__device__ float  g_y  [(size_t)N_NODES_MAX * HID];  // post-aggregation activations
__device__ float  g_dis[N_NODES_MAX];
__device__ int    g_deg[N_NODES_MAX];
__device__ int    g_rowoff[N_NODES_MAX];
__device__ int    g_cursor[N_NODES_MAX];
__device__ int    g_src[N_EDGES_MAX];
__device__ int    g_dst[N_EDGES_MAX];
__device__ int    g_csr[N_EDGES_MAX];
__device__ int    g_is32;
__device__ double g_sum[HID];
__device__ double g_sumsq[HID];
__device__ float  g_bns[HID];   // BN scale  (gamma * rsqrt(var+eps))
__device__ float  g_bnt[HID];   // BN shift  (beta - mean*scale)

// ---------------- prep ----------------
__global__ void init_kernel(int n) {
    int i = blockIdx.x * blockDim.x + threadIdx.x;
    if (i < n) g_deg[i] = 0;
    if (i == 0) g_is32 = 0;
    if (i < HID) { g_sum[i] = 0.0; g_sumsq[i] = 0.0; }
}

// Scan first E 64-bit words (safe for both int32[2E] and int64[2E] buffers).
// Genuine int64 indices are all < M; packed int32 pairs mostly exceed 2^32.
__global__ void detect_kernel(const unsigned long long* __restrict__ p,
                              int E, int M) {
    int i = blockIdx.x * blockDim.x + threadIdx.x;
    if (i < E && p[i] >= (unsigned long long)M) g_is32 = 1;
}

__global__ void convert_kernel(const void* __restrict__ ei, int E) {
    int e = blockIdx.x * blockDim.x + threadIdx.x;
    if (e >= E) return;
    int s, d;
    if (g_is32) {
        const int* p = (const int*)ei;
        s = p[e]; d = p[E + e];
    } else {
        const long long* p = (const long long*)ei;
        s = (int)p[e]; d = (int)p[(size_t)E + e];
    }
    g_src[e] = s;
    g_dst[e] = d;
    atomicAdd(&g_deg[d], 1);
}

// Single-block exclusive scan of degrees -> row offsets + cursors + dis.
__global__ void __launch_bounds__(1024)
scan_kernel(int M) {
    __shared__ int part[1024];
    const int t = threadIdx.x;
    const int chunk = (M + 1023) >> 10;
    const int base = t * chunk;
    int s = 0;
    for (int i = 0; i < chunk; i++) {
        int idx = base + i;
        if (idx < M) s += g_deg[idx];
    }
    part[t] = s;
    __syncthreads();
    for (int off = 1; off < 1024; off <<= 1) {
        int v = (t >= off) ? part[t - off] : 0;
        __syncthreads();
        part[t] += v;
        __syncthreads();
    }
    int run = (t == 0) ? 0 : part[t - 1];
    for (int i = 0; i < chunk; i++) {
        int idx = base + i;
        if (idx < M) {
            int d = g_deg[idx];
            g_rowoff[idx] = run;
            g_cursor[idx] = run;
            g_dis[idx] = rsqrtf((float)(d + 1));   // +1 = self loop
            run += d;
        }
    }
}

__global__ void fill_kernel(int E) {
    int e = blockIdx.x * blockDim.x + threadIdx.x;
    if (e >= E) return;
    int d = g_dst[e];
    int pos = atomicAdd(&g_cursor[d], 1);
    g_csr[pos] = g_src[e];
}

// ---------------- GEMM: C[M,256] = op(A)[M,K] @ W[K,256] ----------------
// 128x64 tile, 8x4 micro-tile, double-buffered SMEM.
// op(A): optional per-K-column affine (BN folded into the A load).
// Epilogue: optional *dis[row]; optional +bias[col].
template<int K, bool AFFINE, bool SCALE_ROW, bool ADD_BIAS>
__global__ void __launch_bounds__(256, 2)
gemm128(const float* __restrict__ A, const float* __restrict__ W,
        float* __restrict__ C, int M, const float* __restrict__ bias)
{
    constexpr int NK = K / 16;
    __shared__ float As[2][16][132];   // [buf][k][row] (128 rows, padded)
    __shared__ float Bs[2][16][68];    // [buf][k][col] (64 cols, padded)

    const int tid = threadIdx.x;
    const int rowBase = blockIdx.x * 128;
    const int colBase = blockIdx.y * 64;

    const int ar = tid >> 2;           // 0..63 (and +64)
    const int ac = (tid & 3) * 4;      // 0,4,8,12
    const int br = tid >> 4;           // 0..15
    const int bc = (tid & 15) * 4;     // 0..60
    const int ty = tid >> 4;           // rows ty*8 .. +7
    const int tx = tid & 15;           // cols tx*4 .. +3

    const bool v0 = (rowBase + ar) < M;
    const bool v1 = (rowBase + ar + 64) < M;
    const float* Ap0 = A + (size_t)(rowBase + ar) * K + ac;
    const float* Ap1 = A + (size_t)(rowBase + ar + 64) * K + ac;
    const float* Wp  = W + (size_t)br * HID + colBase + bc;

    float4 ra0, ra1, rb;
    const float4 zf4 = make_float4(0.f, 0.f, 0.f, 0.f);

    // ---- load tile 0 ----
    ra0 = v0 ? *(const float4*)(Ap0) : zf4;
    ra1 = v1 ? *(const float4*)(Ap1) : zf4;
    if (AFFINE) {
        float4 s = *(const float4*)(g_bns + ac);
        float4 t = *(const float4*)(g_bnt + ac);
        ra0.x = fmaf(ra0.x, s.x, t.x); ra0.y = fmaf(ra0.y, s.y, t.y);
        ra0.z = fmaf(ra0.z, s.z, t.z); ra0.w = fmaf(ra0.w, s.w, t.w);
        ra1.x = fmaf(ra1.x, s.x, t.x); ra1.y = fmaf(ra1.y, s.y, t.y);
        ra1.z = fmaf(ra1.z, s.z, t.z); ra1.w = fmaf(ra1.w, s.w, t.w);
    }
    rb = *(const float4*)(Wp);

    As[0][ac + 0][ar] = ra0.x; As[0][ac + 1][ar] = ra0.y;
    As[0][ac + 2][ar] = ra0.z; As[0][ac + 3][ar] = ra0.w;
    As[0][ac + 0][ar + 64] = ra1.x; As[0][ac + 1][ar + 64] = ra1.y;
    As[0][ac + 2][ar + 64] = ra1.z; As[0][ac + 3][ar + 64] = ra1.w;
    *(float4*)&Bs[0][br][bc] = rb;
    __syncthreads();

    float acc[8][4] = {};

    for (int kt = 0; kt < NK; kt++) {
        const int buf = kt & 1;
        if (kt + 1 < NK) {
            const int ko = (kt + 1) * 16;
            ra0 = v0 ? *(const float4*)(Ap0 + ko) : zf4;
            ra1 = v1 ? *(const float4*)(Ap1 + ko) : zf4;
            if (AFFINE) {
                float4 s = *(const float4*)(g_bns + ko + ac);
                float4 t = *(const float4*)(g_bnt + ko + ac);
                ra0.x = fmaf(ra0.x, s.x, t.x); ra0.y = fmaf(ra0.y, s.y, t.y);
                ra0.z = fmaf(ra0.z, s.z, t.z); ra0.w = fmaf(ra0.w, s.w, t.w);
                ra1.x = fmaf(ra1.x, s.x, t.x); ra1.y = fmaf(ra1.y, s.y, t.y);
                ra1.z = fmaf(ra1.z, s.z, t.z); ra1.w = fmaf(ra1.w, s.w, t.w);
            }
            rb = *(const float4*)(Wp + (size_t)ko * HID);
        }

        #pragma unroll
        for (int k = 0; k < 16; k++) {
            float a[8], b[4];
            *(float4*)&a[0] = *(const float4*)&As[buf][k][ty * 8];
            *(float4*)&a[4] = *(const float4*)&As[buf][k][ty * 8 + 4];
            *(float4*)&b[0] = *(const float4*)&Bs[buf][k][tx * 4];
            #pragma unroll
            for (int i = 0; i < 8; i++)
                #pragma unroll
                for (int j = 0; j < 4; j++)
                    acc[i][j] = fmaf(a[i], b[j], acc[i][j]);
        }

        if (kt + 1 < NK) {
            __syncthreads();
            const int nb = buf ^ 1;
            As[nb][ac + 0][ar] = ra0.x; As[nb][ac + 1][ar] = ra0.y;
            As[nb][ac + 2][ar] = ra0.z; As[nb][ac + 3][ar] = ra0.w;
            As[nb][ac + 0][ar + 64] = ra1.x; As[nb][ac + 1][ar + 64] = ra1.y;
            As[nb][ac + 2][ar + 64] = ra1.z; As[nb][ac + 3][ar + 64] = ra1.w;
            *(float4*)&Bs[nb][br][bc] = rb;
            __syncthreads();
        }
    }

    float4 bv = zf4;
    if (ADD_BIAS) bv = *(const float4*)(bias + colBase + tx * 4);

    #pragma unroll
    for (int i = 0; i < 8; i++) {
        int grow = rowBase + ty * 8 + i;
        if (grow >= M) continue;
        float d = SCALE_ROW ? g_dis[grow] : 1.f;
        float4 o;
        o.x = acc[i][0]; o.y = acc[i][1]; o.z = acc[i][2]; o.w = acc[i][3];
        if (SCALE_ROW) { o.x *= d; o.y *= d; o.z *= d; o.w *= d; }
        if (ADD_BIAS)  { o.x += bv.x; o.y += bv.y; o.z += bv.z; o.w += bv.w; }
        *(float4*)(C + (size_t)grow * HID + colBase + tx * 4) = o;
    }
}

// ---------------- CSR gather + combine + BN statistics ----------------
// One warp per node (grid-stride): y[i] = dis_i * (h'[i] + sum_{j->i} h'[j]).
// No feature atomics. Column stats reduced via shared doubles.
__global__ void __launch_bounds__(256)
gather_stats(const float* __restrict__ h, float* __restrict__ y, int M)
{
    __shared__ double sh[8][HID];

    const int tid  = threadIdx.x;
    const int lane = tid & 31;
    const int wid  = tid >> 5;
    const int gwarp = (blockIdx.x * blockDim.x + tid) >> 5;
    const int nwarp = (gridDim.x * blockDim.x) >> 5;

    float ds[8]  = {};
    float dsq[8] = {};

    for (int n = gwarp; n < M; n += nwarp) {
        const float4* self = (const float4*)(h + (size_t)n * HID);
        float4 a0 = __ldg(self + lane);
        float4 a1 = __ldg(self + lane + 32);

        const int roff = g_rowoff[n];
        const int dcnt = g_deg[n];
        int j = 0;
        for (; j + 1 < dcnt; j += 2) {
            int s0 = __ldg(g_csr + roff + j);
            int s1 = __ldg(g_csr + roff + j + 1);
            const float4* p0 = (const float4*)(h + (size_t)s0 * HID);
            const float4* p1 = (const float4*)(h + (size_t)s1 * HID);
            float4 b0 = __ldg(p0 + lane);
            float4 b1 = __ldg(p0 + lane + 32);
            float4 c0 = __ldg(p1 + lane);
            float4 c1 = __ldg(p1 + lane + 32);
            a0.x += b0.x + c0.x; a0.y += b0.y + c0.y;
            a0.z += b0.z + c0.z; a0.w += b0.w + c0.w;
            a1.x += b1.x + c1.x; a1.y += b1.y + c1.y;
            a1.z += b1.z + c1.z; a1.w += b1.w + c1.w;
        }
        if (j < dcnt) {
            int s0 = __ldg(g_csr + roff + j);
            const float4* p0 = (const float4*)(h + (size_t)s0 * HID);
            float4 b0 = __ldg(p0 + lane);
            float4 b1 = __ldg(p0 + lane + 32);
            a0.x += b0.x; a0.y += b0.y; a0.z += b0.z; a0.w += b0.w;
            a1.x += b1.x; a1.y += b1.y; a1.z += b1.z; a1.w += b1.w;
        }

        const float di = g_dis[n];
        a0.x *= di; a0.y *= di; a0.z *= di; a0.w *= di;
        a1.x *= di; a1.y *= di; a1.z *= di; a1.w *= di;

        float4* yp = (float4*)(y + (size_t)n * HID);
        yp[lane] = a0;
        yp[lane + 32] = a1;

        ds[0] += a0.x; dsq[0] += a0.x * a0.x;
        ds[1] += a0.y; dsq[1] += a0.y * a0.y;
        ds[2] += a0.z; dsq[2] += a0.z * a0.z;
        ds[3] += a0.w; dsq[3] += a0.w * a0.w;
        ds[4] += a1.x; dsq[4] += a1.x * a1.x;
        ds[5] += a1.y; dsq[5] += a1.y * a1.y;
        ds[6] += a1.z; dsq[6] += a1.z * a1.z;
        ds[7] += a1.w; dsq[7] += a1.w * a1.w;
    }

    // column map: k<4 -> lane*4+k ; k>=4 -> 128 + lane*4 + (k-4)
    #pragma unroll
    for (int k = 0; k < 8; k++) {
        int col = (k < 4) ? (lane * 4 + k) : (128 + lane * 4 + (k - 4));
        sh[wid][col] = (double)ds[k];
    }
    __syncthreads();
    {
        double s = 0.0;
        #pragma unroll
        for (int w = 0; w < 8; w++) s += sh[w][tid];
        atomicAdd(&g_sum[tid], s);
    }
    __syncthreads();
    #pragma unroll
    for (int k = 0; k < 8; k++) {
        int col = (k < 4) ? (lane * 4 + k) : (128 + lane * 4 + (k - 4));
        sh[wid][col] = (double)dsq[k];
    }
    __syncthreads();
    {
        double s = 0.0;
        #pragma unroll
        for (int w = 0; w < 8; w++) s += sh[w][tid];
        atomicAdd(&g_sumsq[tid], s);
    }
}

// ---------------- BN finalize: fold (mean,var,gamma,beta) into affine ------
// Pre-BN bias (b1/b2) cancels under BN mean subtraction, so omitted.
__global__ void bn_finalize(const float* __restrict__ gamma,
                            const float* __restrict__ beta, int M)
{
    int c = threadIdx.x;
    double m   = g_sum[c] / (double)M;
    double var = g_sumsq[c] / (double)M - m * m;
    float sc = gamma[c] * rsqrtf((float)var + BN_EPS);
    g_bns[c] = sc;
    g_bnt[c] = beta[c] - (float)m * sc;
    g_sum[c] = 0.0; g_sumsq[c] = 0.0;   // ready for next layer's stats
}

// ---------------- launch ----------------
extern "C" void kernel_launch(void* const* d_in, const int* in_sizes, int n_in,
                              void* d_out, int out_size)
{
    const float* x   = (const float*)d_in[0];
    const void*  ei  = d_in[1];
    const float* W1  = (const float*)d_in[2];
    // d_in[3] = b1 (cancels in BN)
    const float* g1  = (const float*)d_in[4];
    const float* be1 = (const float*)d_in[5];
    const float* W2  = (const float*)d_in[6];
    // d_in[7] = b2 (cancels in BN)
    const float* g2  = (const float*)d_in[8];
    const float* be2 = (const float*)d_in[9];
    const float* Wfc = (const float*)d_in[10];
    const float* bfc = (const float*)d_in[11];
    float* out = (float*)d_out;

    const int M = in_sizes[0] / NFEAT;   // 50000
    const int E = in_sizes[1] / 2;       // 800000

    void *p_h, *p_y;
    cudaGetSymbolAddress(&p_h, g_h);
    cudaGetSymbolAddress(&p_y, g_y);
    float* h = (float*)p_h;
    float* y = (float*)p_y;

    const int TB = 256;
    dim3 gemmGrid((M + 127) / 128, HID / 64);
    const int gatherBlocks = 592;   // 4736 warps

    // edge decode (dtype-robust) + CSR build + normalization coefficients
    init_kernel<<<(M + TB - 1) / TB, TB>>>(M);
    detect_kernel<<<(E + TB - 1) / TB, TB>>>((const unsigned long long*)ei, E, M);
    convert_kernel<<<(E + TB - 1) / TB, TB>>>(ei, E);
    scan_kernel<<<1, 1024>>>(M);
    fill_kernel<<<(E + TB - 1) / TB, TB>>>(E);

    // ---- layer 1: GCNConv(x, W1) + BN1 (folded) ----
    gemm128<NFEAT, false, true, false><<<gemmGrid, TB>>>(x, W1, h, M, nullptr);
    gather_stats<<<gatherBlocks, TB>>>(h, y, M);
    bn_finalize<<<1, HID>>>(g1, be1, M);

    // ---- layer 2: GCNConv(bn1(y), W2) + BN2 (folded) ----
    gemm128<HID, true, true, false><<<gemmGrid, TB>>>(y, W2, h, M, nullptr);
    gather_stats<<<gatherBlocks, TB>>>(h, y, M);
    bn_finalize<<<1, HID>>>(g2, be2, M);

    // ---- FC: out = bn2(y) @ Wfc + bfc ----
    gemm128<HID, true, false, true><<<gemmGrid, TB>>>(y, Wfc, out, M, bfc);
}

// round 4
// speedup vs baseline: 2.5294x; 1.1155x over previous
#include <cuda_runtime.h>

#define N_NODES_MAX 50000
#define N_EDGES_MAX 800000
#define NFEAT 128
#define HID 256
#define BN_EPS 1e-5f

// ---------------- scratch (static __device__, no allocation) ----------------
__device__ float  g_h  [(size_t)N_NODES_MAX * HID];  // h' = (opA@W) * dis[row]
__device__ float  g_y  [(size_t)N_NODES_MAX * HID];  // post-aggregation activations
__device__ float  g_dis[N_NODES_MAX];
__device__ int    g_deg[N_NODES_MAX];
__device__ int    g_rowoff[N_NODES_MAX];
__device__ int    g_cursor[N_NODES_MAX];
__device__ int    g_src[N_EDGES_MAX];
__device__ int    g_dst[N_EDGES_MAX];
__device__ int    g_csr[N_EDGES_MAX];
__device__ int    g_part[256];        // per-block degree sums
__device__ int    g_partscan[256];    // exclusive scan of g_part
__device__ int    g_is32;
__device__ double g_sum[HID];
__device__ double g_sumsq[HID];
__device__ float  g_bns[HID];   // BN scale  (gamma * rsqrt(var+eps))
__device__ float  g_bnt[HID];   // BN shift  (beta - mean*scale)

// ---------------- prep ----------------
__global__ void init_kernel(int n) {
    int i = blockIdx.x * blockDim.x + threadIdx.x;
    if (i < n) g_deg[i] = 0;
    if (i == 0) g_is32 = 0;
    if (i < HID) { g_sum[i] = 0.0; g_sumsq[i] = 0.0; }
}

// Scan first E 64-bit words (safe for both int32[2E] and int64[2E] buffers).
// Genuine int64 indices are all < M; packed int32 pairs mostly exceed 2^32.
__global__ void detect_kernel(const unsigned long long* __restrict__ p,
                              int E, int M) {
    int i = blockIdx.x * blockDim.x + threadIdx.x;
    if (i < E && p[i] >= (unsigned long long)M) g_is32 = 1;
}

__global__ void convert_kernel(const void* __restrict__ ei, int E) {
    int e = blockIdx.x * blockDim.x + threadIdx.x;
    if (e >= E) return;
    int s, d;
    if (g_is32) {
        const int* p = (const int*)ei;
        s = p[e]; d = p[E + e];
    } else {
        const long long* p = (const long long*)ei;
        s = (int)p[e]; d = (int)p[(size_t)E + e];
    }
    g_src[e] = s;
    g_dst[e] = d;
    atomicAdd(&g_deg[d], 1);
}

// ---- hierarchical scan: partial sums -> scan partials -> local scan ----
__global__ void __launch_bounds__(256)
partsum_kernel(int M) {
    __shared__ int sh[8];
    const int tid = threadIdx.x;
    int i = blockIdx.x * 256 + tid;
    int d = (i < M) ? g_deg[i] : 0;
    int v = d;
    #pragma unroll
    for (int o = 16; o > 0; o >>= 1) v += __shfl_down_sync(~0u, v, o);
    if ((tid & 31) == 0) sh[tid >> 5] = v;
    __syncthreads();
    if (tid < 8) {
        int w = sh[tid];
        #pragma unroll
        for (int o = 4; o > 0; o >>= 1) w += __shfl_down_sync(0xffu, w, o);
        if (tid == 0) g_part[blockIdx.x] = w;
    }
}

__global__ void __launch_bounds__(256)
scanpart_kernel(int NB) {
    __shared__ int sh[256];
    const int t = threadIdx.x;
    sh[t] = (t < NB) ? g_part[t] : 0;
    __syncthreads();
    for (int off = 1; off < 256; off <<= 1) {
        int v = (t >= off) ? sh[t - off] : 0;
        __syncthreads();
        sh[t] += v;
        __syncthreads();
    }
    if (t < NB) g_partscan[t] = (t == 0) ? 0 : sh[t - 1];
}

__global__ void __launch_bounds__(256)
scanfinal_kernel(int M) {
    __shared__ int sh[8];
    const int tid = threadIdx.x;
    int i = blockIdx.x * 256 + tid;
    int d = (i < M) ? g_deg[i] : 0;
    // intra-warp inclusive scan
    int v = d;
    #pragma unroll
    for (int o = 1; o < 32; o <<= 1) {
        int u = __shfl_up_sync(~0u, v, o);
        if ((tid & 31) >= o) v += u;
    }
    if ((tid & 31) == 31) sh[tid >> 5] = v;
    __syncthreads();
    if (tid < 8) {
        int w = sh[tid];
        #pragma unroll
        for (int o = 1; o < 8; o <<= 1) {
            int u = __shfl_up_sync(0xffu, w, o);
            if (tid >= o) w += u;
        }
        sh[tid] = w;
    }
    __syncthreads();
    int warpBase = (tid >= 32) ? sh[(tid >> 5) - 1] : 0;
    int excl = g_partscan[blockIdx.x] + warpBase + v - d;
    if (i < M) {
        g_rowoff[i] = excl;
        g_cursor[i] = excl;
        g_dis[i] = rsqrtf((float)(d + 1));   // +1 = self loop
    }
}

__global__ void fill_kernel(int E) {
    int e = blockIdx.x * blockDim.x + threadIdx.x;
    if (e >= E) return;
    int d = g_dst[e];
    int pos = atomicAdd(&g_cursor[d], 1);
    g_csr[pos] = g_src[e];
}

// ---------------- GEMM: C[M,256] = op(A)[M,K] @ W[K,256] ----------------
// 128x128 tile, 8x8 micro-tile, double-buffered SMEM.
// op(A): optional per-K-column affine (BN folded into the A load).
// Epilogue: optional *dis[row]; optional +bias[col].
template<int K, bool AFFINE, bool SCALE_ROW, bool ADD_BIAS>
__global__ void __launch_bounds__(256, 2)
gemm128(const float* __restrict__ A, const float* __restrict__ W,
        float* __restrict__ C, int M, const float* __restrict__ bias)
{
    constexpr int NK = K / 16;
    __shared__ float As[2][16][132];   // [buf][k][row] (128 rows, padded)
    __shared__ float Bs[2][16][132];   // [buf][k][col] (128 cols, padded)

    const int tid = threadIdx.x;
    const int rowBase = blockIdx.x * 128;
    const int colBase = blockIdx.y * 128;

    const int ar = tid >> 2;           // 0..63 (and +64)
    const int ac = (tid & 3) * 4;      // 0,4,8,12
    const int br = tid >> 4;           // 0..15
    const int bc = (tid & 15) * 4;     // 0..60 (and +64)
    const int ty = tid >> 4;           // rows ty*8 .. +7
    const int tx = tid & 15;           // cols tx*8 .. +7

    const bool v0 = (rowBase + ar) < M;
    const bool v1 = (rowBase + ar + 64) < M;
    const float* Ap0 = A + (size_t)(rowBase + ar) * K + ac;
    const float* Ap1 = A + (size_t)(rowBase + ar + 64) * K + ac;
    const float* Wp  = W + (size_t)br * HID + colBase + bc;

    float4 ra0, ra1, rb0, rb1;
    const float4 zf4 = make_float4(0.f, 0.f, 0.f, 0.f);

    // ---- load tile 0 ----
    ra0 = v0 ? *(const float4*)(Ap0) : zf4;
    ra1 = v1 ? *(const float4*)(Ap1) : zf4;
    if (AFFINE) {
        float4 s = *(const float4*)(g_bns + ac);
        float4 t = *(const float4*)(g_bnt + ac);
        ra0.x = fmaf(ra0.x, s.x, t.x); ra0.y = fmaf(ra0.y, s.y, t.y);
        ra0.z = fmaf(ra0.z, s.z, t.z); ra0.w = fmaf(ra0.w, s.w, t.w);
        ra1.x = fmaf(ra1.x, s.x, t.x); ra1.y = fmaf(ra1.y, s.y, t.y);
        ra1.z = fmaf(ra1.z, s.z, t.z); ra1.w = fmaf(ra1.w, s.w, t.w);
    }
    rb0 = *(const float4*)(Wp);
    rb1 = *(const float4*)(Wp + 64);

    As[0][ac + 0][ar] = ra0.x; As[0][ac + 1][ar] = ra0.y;
    As[0][ac + 2][ar] = ra0.z; As[0][ac + 3][ar] = ra0.w;
    As[0][ac + 0][ar + 64] = ra1.x; As[0][ac + 1][ar + 64] = ra1.y;
    As[0][ac + 2][ar + 64] = ra1.z; As[0][ac + 3][ar + 64] = ra1.w;
    *(float4*)&Bs[0][br][bc] = rb0;
    *(float4*)&Bs[0][br][bc + 64] = rb1;
    __syncthreads();

    float acc[8][8] = {};

    for (int kt = 0; kt < NK; kt++) {
        const int buf = kt & 1;
        if (kt + 1 < NK) {
            const int ko = (kt + 1) * 16;
            ra0 = v0 ? *(const float4*)(Ap0 + ko) : zf4;
            ra1 = v1 ? *(const float4*)(Ap1 + ko) : zf4;
            if (AFFINE) {
                float4 s = *(const float4*)(g_bns + ko + ac);
                float4 t = *(const float4*)(g_bnt + ko + ac);
                ra0.x = fmaf(ra0.x, s.x, t.x); ra0.y = fmaf(ra0.y, s.y, t.y);
                ra0.z = fmaf(ra0.z, s.z, t.z); ra0.w = fmaf(ra0.w, s.w, t.w);
                ra1.x = fmaf(ra1.x, s.x, t.x); ra1.y = fmaf(ra1.y, s.y, t.y);
                ra1.z = fmaf(ra1.z, s.z, t.z); ra1.w = fmaf(ra1.w, s.w, t.w);
            }
            rb0 = *(const float4*)(Wp + (size_t)ko * HID);
            rb1 = *(const float4*)(Wp + (size_t)ko * HID + 64);
        }

        #pragma unroll
        for (int k = 0; k < 16; k++) {
            float a[8], b[8];
            *(float4*)&a[0] = *(const float4*)&As[buf][k][ty * 8];
            *(float4*)&a[4] = *(const float4*)&As[buf][k][ty * 8 + 4];
            *(float4*)&b[0] = *(const float4*)&Bs[buf][k][tx * 8];
            *(float4*)&b[4] = *(const float4*)&Bs[buf][k][tx * 8 + 4];
            #pragma unroll
            for (int i = 0; i < 8; i++)
                #pragma unroll
                for (int j = 0; j < 8; j++)
                    acc[i][j] = fmaf(a[i], b[j], acc[i][j]);
        }

        if (kt + 1 < NK) {
            __syncthreads();
            const int nb = buf ^ 1;
            As[nb][ac + 0][ar] = ra0.x; As[nb][ac + 1][ar] = ra0.y;
            As[nb][ac + 2][ar] = ra0.z; As[nb][ac + 3][ar] = ra0.w;
            As[nb][ac + 0][ar + 64] = ra1.x; As[nb][ac + 1][ar + 64] = ra1.y;
            As[nb][ac + 2][ar + 64] = ra1.z; As[nb][ac + 3][ar + 64] = ra1.w;
            *(float4*)&Bs[nb][br][bc] = rb0;
            *(float4*)&Bs[nb][br][bc + 64] = rb1;
            __syncthreads();
        }
    }

    float4 bv0 = zf4, bv1 = zf4;
    if (ADD_BIAS) {
        bv0 = *(const float4*)(bias + colBase + tx * 8);
        bv1 = *(const float4*)(bias + colBase + tx * 8 + 4);
    }

    #pragma unroll
    for (int i = 0; i < 8; i++) {
        int grow = rowBase + ty * 8 + i;
        if (grow >= M) continue;
        float d = SCALE_ROW ? g_dis[grow] : 1.f;
        float4 o0, o1;
        o0.x = acc[i][0]; o0.y = acc[i][1]; o0.z = acc[i][2]; o0.w = acc[i][3];
        o1.x = acc[i][4]; o1.y = acc[i][5]; o1.z = acc[i][6]; o1.w = acc[i][7];
        if (SCALE_ROW) {
            o0.x *= d; o0.y *= d; o0.z *= d; o0.w *= d;
            o1.x *= d; o1.y *= d; o1.z *= d; o1.w *= d;
        }
        if (ADD_BIAS) {
            o0.x += bv0.x; o0.y += bv0.y; o0.z += bv0.z; o0.w += bv0.w;
            o1.x += bv1.x; o1.y += bv1.y; o1.z += bv1.z; o1.w += bv1.w;
        }
        float* cp = C + (size_t)grow * HID + colBase + tx * 8;
        *(float4*)(cp) = o0;
        *(float4*)(cp + 4) = o1;
    }
}

// ---------------- CSR gather + combine + BN statistics ----------------
// One warp per node (grid-stride): y[i] = dis_i * (h'[i] + sum_{j->i} h'[j]).
// No feature atomics. Column stats reduced via shared doubles.
__global__ void __launch_bounds__(256)
gather_stats(const float* __restrict__ h, float* __restrict__ y, int M)
{
    __shared__ double sh[8][HID];

    const int tid  = threadIdx.x;
    const int lane = tid & 31;
    const int wid  = tid >> 5;
    const int gwarp = (blockIdx.x * blockDim.x + tid) >> 5;
    const int nwarp = (gridDim.x * blockDim.x) >> 5;

    float ds[8]  = {};
    float dsq[8] = {};

    for (int n = gwarp; n < M; n += nwarp) {
        const float4* self = (const float4*)(h + (size_t)n * HID);
        float4 a0 = __ldg(self + lane);
        float4 a1 = __ldg(self + lane + 32);

        const int roff = g_rowoff[n];
        const int dcnt = g_deg[n];
        int j = 0;
        for (; j + 1 < dcnt; j += 2) {
            int s0 = __ldg(g_csr + roff + j);
            int s1 = __ldg(g_csr + roff + j + 1);
            const float4* p0 = (const float4*)(h + (size_t)s0 * HID);
            const float4* p1 = (const float4*)(h + (size_t)s1 * HID);
            float4 b0 = __ldg(p0 + lane);
            float4 b1 = __ldg(p0 + lane + 32);
            float4 c0 = __ldg(p1 + lane);
            float4 c1 = __ldg(p1 + lane + 32);
            a0.x += b0.x + c0.x; a0.y += b0.y + c0.y;
            a0.z += b0.z + c0.z; a0.w += b0.w + c0.w;
            a1.x += b1.x + c1.x; a1.y += b1.y + c1.y;
            a1.z += b1.z + c1.z; a1.w += b1.w + c1.w;
        }
        if (j < dcnt) {
            int s0 = __ldg(g_csr + roff + j);
            const float4* p0 = (const float4*)(h + (size_t)s0 * HID);
            float4 b0 = __ldg(p0 + lane);
            float4 b1 = __ldg(p0 + lane + 32);
            a0.x += b0.x; a0.y += b0.y; a0.z += b0.z; a0.w += b0.w;
            a1.x += b1.x; a1.y += b1.y; a1.z += b1.z; a1.w += b1.w;
        }

        const float di = g_dis[n];
        a0.x *= di; a0.y *= di; a0.z *= di; a0.w *= di;
        a1.x *= di; a1.y *= di; a1.z *= di; a1.w *= di;

        float4* yp = (float4*)(y + (size_t)n * HID);
        yp[lane] = a0;
        yp[lane + 32] = a1;

        ds[0] += a0.x; dsq[0] += a0.x * a0.x;
        ds[1] += a0.y; dsq[1] += a0.y * a0.y;
        ds[2] += a0.z; dsq[2] += a0.z * a0.z;
        ds[3] += a0.w; dsq[3] += a0.w * a0.w;
        ds[4] += a1.x; dsq[4] += a1.x * a1.x;
        ds[5] += a1.y; dsq[5] += a1.y * a1.y;
        ds[6] += a1.z; dsq[6] += a1.z * a1.z;
        ds[7] += a1.w; dsq[7] += a1.w * a1.w;
    }

    // column map: k<4 -> lane*4+k ; k>=4 -> 128 + lane*4 + (k-4)
    #pragma unroll
    for (int k = 0; k < 8; k++) {
        int col = (k < 4) ? (lane * 4 + k) : (128 + lane * 4 + (k - 4));
        sh[wid][col] = (double)ds[k];
    }
    __syncthreads();
    {
        double s = 0.0;
        #pragma unroll
        for (int w = 0; w < 8; w++) s += sh[w][tid];
        atomicAdd(&g_sum[tid], s);
    }
    __syncthreads();
    #pragma unroll
    for (int k = 0; k < 8; k++) {
        int col = (k < 4) ? (lane * 4 + k) : (128 + lane * 4 + (k - 4));
        sh[wid][col] = (double)dsq[k];
    }
    __syncthreads();
    {
        double s = 0.0;
        #pragma unroll
        for (int w = 0; w < 8; w++) s += sh[w][tid];
        atomicAdd(&g_sumsq[tid], s);
    }
}

// ---------------- BN finalize: fold (mean,var,gamma,beta) into affine ------
// Pre-BN bias (b1/b2) cancels under BN mean subtraction, so omitted.
__global__ void bn_finalize(const float* __restrict__ gamma,
                            const float* __restrict__ beta, int M)
{
    int c = threadIdx.x;
    double m   = g_sum[c] / (double)M;
    double var = g_sumsq[c] / (double)M - m * m;
    float sc = gamma[c] * rsqrtf((float)var + BN_EPS);
    g_bns[c] = sc;
    g_bnt[c] = beta[c] - (float)m * sc;
    g_sum[c] = 0.0; g_sumsq[c] = 0.0;   // ready for next layer's stats
}

// ---------------- launch ----------------
extern "C" void kernel_launch(void* const* d_in, const int* in_sizes, int n_in,
                              void* d_out, int out_size)
{
    const float* x   = (const float*)d_in[0];
    const void*  ei  = d_in[1];
    const float* W1  = (const float*)d_in[2];
    // d_in[3] = b1 (cancels in BN)
    const float* g1  = (const float*)d_in[4];
    const float* be1 = (const float*)d_in[5];
    const float* W2  = (const float*)d_in[6];
    // d_in[7] = b2 (cancels in BN)
    const float* g2  = (const float*)d_in[8];
    const float* be2 = (const float*)d_in[9];
    const float* Wfc = (const float*)d_in[10];
    const float* bfc = (const float*)d_in[11];
    float* out = (float*)d_out;

    const int M = in_sizes[0] / NFEAT;   // 50000
    const int E = in_sizes[1] / 2;       // 800000

    void *p_h, *p_y;
    cudaGetSymbolAddress(&p_h, g_h);
    cudaGetSymbolAddress(&p_y, g_y);
    float* h = (float*)p_h;
    float* y = (float*)p_y;

    const int TB = 256;
    const int NB = (M + 255) / 256;      // scan blocks (<=256)
    dim3 gemmGrid((M + 127) / 128, HID / 128);
    const int gatherBlocks = 592;        // 4736 warps

    // edge decode (dtype-robust) + CSR build + normalization coefficients
    init_kernel<<<(M + TB - 1) / TB, TB>>>(M);
    detect_kernel<<<(E + TB - 1) / TB, TB>>>((const unsigned long long*)ei, E, M);
    convert_kernel<<<(E + TB - 1) / TB, TB>>>(ei, E);
    partsum_kernel<<<NB, 256>>>(M);
    scanpart_kernel<<<1, 256>>>(NB);
    scanfinal_kernel<<<NB, 256>>>(M);
    fill_kernel<<<(E + TB - 1) / TB, TB>>>(E);

    // ---- layer 1: GCNConv(x, W1) + BN1 (folded) ----
    gemm128<NFEAT, false, true, false><<<gemmGrid, TB>>>(x, W1, h, M, nullptr);
    gather_stats<<<gatherBlocks, TB>>>(h, y, M);
    bn_finalize<<<1, HID>>>(g1, be1, M);

    // ---- layer 2: GCNConv(bn1(y), W2) + BN2 (folded) ----
    gemm128<HID, true, true, false><<<gemmGrid, TB>>>(y, W2, h, M, nullptr);
    gather_stats<<<gatherBlocks, TB>>>(h, y, M);
    bn_finalize<<<1, HID>>>(g2, be2, M);

    // ---- FC: out = bn2(y) @ Wfc + bfc ----
    gemm128<HID, true, false, true><<<gemmGrid, TB>>>(y, Wfc, out, M, bfc);
}

// round 5
// speedup vs baseline: 2.6814x; 1.0601x over previous
#include <cuda_runtime.h>
#include <cuda_bf16.h>
#include <cstdint>

#define N_NODES_MAX 50000
#define N_EDGES_MAX 800000
#define NFEAT 128
#define HID 256
#define BN_EPS 1e-5f

typedef __nv_bfloat16 bf16;

// ---------------- scratch (static __device__, no allocation) ----------------
__device__ float  g_h  [(size_t)N_NODES_MAX * HID];
__device__ float  g_y  [(size_t)N_NODES_MAX * HID];
__device__ bf16   g_ahi[(size_t)N_NODES_MAX * HID];
__device__ bf16   g_alo[(size_t)N_NODES_MAX * HID];
__device__ bf16   g_w1h[HID * NFEAT], g_w1l[HID * NFEAT];     // [N][K] transposed
__device__ bf16   g_w2h[HID * HID],   g_w2l[HID * HID];
__device__ bf16   g_wfh[HID * HID],   g_wfl[HID * HID];
__device__ float  g_dis[N_NODES_MAX];
__device__ int    g_deg[N_NODES_MAX];
__device__ int    g_rowoff[N_NODES_MAX];
__device__ int    g_cursor[N_NODES_MAX];
__device__ int    g_src[N_EDGES_MAX];
__device__ int    g_dst[N_EDGES_MAX];
__device__ int    g_csr[N_EDGES_MAX];
__device__ int    g_part[256];
__device__ int    g_partscan[256];
__device__ int    g_is32;
__device__ double g_sum[HID];
__device__ double g_sumsq[HID];
__device__ float  g_bns[HID];
__device__ float  g_bnt[HID];

// ---------------- prep ----------------
__global__ void init_kernel(int n) {
    int i = blockIdx.x * blockDim.x + threadIdx.x;
    if (i < n) g_deg[i] = 0;
    if (i == 0) g_is32 = 0;
    if (i < HID) { g_sum[i] = 0.0; g_sumsq[i] = 0.0; }
}

__global__ void detect_kernel(const unsigned long long* __restrict__ p,
                              int E, int M) {
    int i = blockIdx.x * blockDim.x + threadIdx.x;
    if (i < E && p[i] >= (unsigned long long)M) g_is32 = 1;
}

__global__ void convert_kernel(const void* __restrict__ ei, int E) {
    int e = blockIdx.x * blockDim.x + threadIdx.x;
    if (e >= E) return;
    int s, d;
    if (g_is32) {
        const int* p = (const int*)ei;
        s = p[e]; d = p[E + e];
    } else {
        const long long* p = (const long long*)ei;
        s = (int)p[e]; d = (int)p[(size_t)E + e];
    }
    g_src[e] = s;
    g_dst[e] = d;
    atomicAdd(&g_deg[d], 1);
}

__global__ void __launch_bounds__(256)
partsum_kernel(int M) {
    __shared__ int sh[8];
    const int tid = threadIdx.x;
    int i = blockIdx.x * 256 + tid;
    int v = (i < M) ? g_deg[i] : 0;
    #pragma unroll
    for (int o = 16; o > 0; o >>= 1) v += __shfl_down_sync(~0u, v, o);
    if ((tid & 31) == 0) sh[tid >> 5] = v;
    __syncthreads();
    if (tid < 8) {
        int w = sh[tid];
        #pragma unroll
        for (int o = 4; o > 0; o >>= 1) w += __shfl_down_sync(0xffu, w, o);
        if (tid == 0) g_part[blockIdx.x] = w;
    }
}

__global__ void __launch_bounds__(256)
scanpart_kernel(int NB) {
    __shared__ int sh[256];
    const int t = threadIdx.x;
    sh[t] = (t < NB) ? g_part[t] : 0;
    __syncthreads();
    for (int off = 1; off < 256; off <<= 1) {
        int v = (t >= off) ? sh[t - off] : 0;
        __syncthreads();
        sh[t] += v;
        __syncthreads();
    }
    if (t < NB) g_partscan[t] = (t == 0) ? 0 : sh[t - 1];
}

__global__ void __launch_bounds__(256)
scanfinal_kernel(int M) {
    __shared__ int sh[8];
    const int tid = threadIdx.x;
    int i = blockIdx.x * 256 + tid;
    int d = (i < M) ? g_deg[i] : 0;
    int v = d;
    #pragma unroll
    for (int o = 1; o < 32; o <<= 1) {
        int u = __shfl_up_sync(~0u, v, o);
        if ((tid & 31) >= o) v += u;
    }
    if ((tid & 31) == 31) sh[tid >> 5] = v;
    __syncthreads();
    if (tid < 8) {
        int w = sh[tid];
        #pragma unroll
        for (int o = 1; o < 8; o <<= 1) {
            int u = __shfl_up_sync(0xffu, w, o);
            if (tid >= o) w += u;
        }
        sh[tid] = w;
    }
    __syncthreads();
    int warpBase = (tid >= 32) ? sh[(tid >> 5) - 1] : 0;
    int excl = g_partscan[blockIdx.x] + warpBase + v - d;
    if (i < M) {
        g_rowoff[i] = excl;
        g_cursor[i] = excl;
        g_dis[i] = rsqrtf((float)(d + 1));
    }
}

__global__ void fill_kernel(int E) {
    int e = blockIdx.x * blockDim.x + threadIdx.x;
    if (e >= E) return;
    int d = g_dst[e];
    int pos = atomicAdd(&g_cursor[d], 1);
    g_csr[pos] = g_src[e];
}

// ---------------- weight split (transposed): wT[n][k] = split(W[k][n]) -----
__global__ void wsplit_kernel(const float* __restrict__ W,
                              bf16* __restrict__ whi, bf16* __restrict__ wlo,
                              int K) {
    int idx = blockIdx.x * blockDim.x + threadIdx.x;
    if (idx >= K * HID) return;
    int k = idx >> 8;          // row in W (K dim)
    int n = idx & 255;         // col in W
    float v = W[idx];
    bf16 h = __float2bfloat16(v);
    bf16 l = __float2bfloat16(v - __bfloat162float(h));
    whi[(size_t)n * K + k] = h;
    wlo[(size_t)n * K + k] = l;
}

// ---------------- activation split: fp32 -> (hi, lo) bf16 ----------------
__device__ __forceinline__ uint32_t pack2(float a, float b) {
    __nv_bfloat162 t = __floats2bfloat162_rn(a, b);
    return *(uint32_t*)&t;
}

template<bool AFFINE>
__global__ void __launch_bounds__(256)
split_kernel(const float* __restrict__ in, bf16* __restrict__ hi,
             bf16* __restrict__ lo, int n4) {
    int i = blockIdx.x * blockDim.x + threadIdx.x;
    if (i >= n4) return;
    float4 v = __ldg((const float4*)in + i);
    if (AFFINE) {
        int c = (i * 4) & 255;
        float4 s = *(const float4*)(g_bns + c);
        float4 t = *(const float4*)(g_bnt + c);
        v.x = fmaf(v.x, s.x, t.x); v.y = fmaf(v.y, s.y, t.y);
        v.z = fmaf(v.z, s.z, t.z); v.w = fmaf(v.w, s.w, t.w);
    }
    float hx = __bfloat162float(__float2bfloat16(v.x));
    float hy = __bfloat162float(__float2bfloat16(v.y));
    float hz = __bfloat162float(__float2bfloat16(v.z));
    float hw = __bfloat162float(__float2bfloat16(v.w));
    uint2 H, L;
    H.x = pack2(v.x, v.y); H.y = pack2(v.z, v.w);
    L.x = pack2(v.x - hx, v.y - hy); L.y = pack2(v.z - hz, v.w - hw);
    *((uint2*)hi + i) = H;
    *((uint2*)lo + i) = L;
}

// ---------------- tensor-core GEMM: C[M,256] = A[M,K] @ WT[256,K]^T -------
// Split-bf16 3-pass: C = Ah*Wh + Ah*Wl + Al*Wh. Block 128x256, 8 warps of
// 64x64. K-chunk 16, cp.async double buffer. Fragment LDS uses 48B row
// stride (12 b32) => bank-conflict-free bijection.
__device__ __forceinline__ void mma16816(float* c, const uint32_t* a,
                                         const uint32_t* b) {
    asm volatile(
        "mma.sync.aligned.m16n8k16.row.col.f32.bf16.bf16.f32 "
        "{%0,%1,%2,%3}, {%4,%5,%6,%7}, {%8,%9}, {%0,%1,%2,%3};"
        : "+f"(c[0]), "+f"(c[1]), "+f"(c[2]), "+f"(c[3])
        : "r"(a[0]), "r"(a[1]), "r"(a[2]), "r"(a[3]), "r"(b[0]), "r"(b[1]));
}

__device__ __forceinline__ void cpa16(void* s, const void* g) {
    uint32_t sa = (uint32_t)__cvta_generic_to_shared(s);
    asm volatile("cp.async.cg.shared.global [%0], [%1], 16;" :: "r"(sa), "l"(g));
}

#define SM_STAGE 36864
#define SM_AL    6144
#define SM_BH    12288
#define SM_BL    24576

template<int K, bool ADD_BIAS>
__global__ void __launch_bounds__(256)
gemm_mma(const bf16* __restrict__ Ahi, const bf16* __restrict__ Alo,
         const bf16* __restrict__ Bhi, const bf16* __restrict__ Blo,
         float* __restrict__ C, int M, const float* __restrict__ bias)
{
    extern __shared__ char smbuf[];
    constexpr int NK = K / 16;
    const int tid = threadIdx.x;
    const int l   = tid & 31;
    const int wid = tid >> 5;
    const int wm  = (wid & 1) * 64;
    const int wn  = (wid >> 1) * 64;
    const int rowBase = blockIdx.x * 128;

    // staging coords
    const int arow  = tid >> 1;
    const int ahalf = tid & 1;
    const int gar   = min(rowBase + arow, M - 1);
    const size_t aoff = (size_t)gar * K + ahalf * 8;
    const int asm_off = arow * 48 + ahalf * 16;

    float acc[4][8][4] = {};

    // ---- cp.async stage issue ----
    auto issue = [&](int kt, int buf) {
        char* st = smbuf + buf * SM_STAGE;
        int ko = kt * 16;
        cpa16(st + asm_off,         Ahi + aoff + ko);
        cpa16(st + SM_AL + asm_off, Alo + aoff + ko);
        #pragma unroll
        for (int q = 0; q < 2; q++) {
            int slot = tid + q * 256;
            int n = slot >> 1, hh = slot & 1;
            size_t boff = (size_t)n * K + ko + hh * 8;
            int so = n * 48 + hh * 16;
            cpa16(st + SM_BH + so, Bhi + boff);
            cpa16(st + SM_BL + so, Blo + boff);
        }
    };

    issue(0, 0);
    asm volatile("cp.async.commit_group;");

    const int kq = l & 3;
    const int rl = l >> 2;

    for (int kt = 0; kt < NK; kt++) {
        const int buf = kt & 1;
        if (kt + 1 < NK) {
            issue(kt + 1, buf ^ 1);
            asm volatile("cp.async.commit_group;");
            asm volatile("cp.async.wait_group 1;");
        } else {
            asm volatile("cp.async.wait_group 0;");
        }
        __syncthreads();

        const bf16* Ah = (const bf16*)(smbuf + buf * SM_STAGE);
        const bf16* Al = (const bf16*)(smbuf + buf * SM_STAGE + SM_AL);
        const bf16* Bh = (const bf16*)(smbuf + buf * SM_STAGE + SM_BH);
        const bf16* Bl = (const bf16*)(smbuf + buf * SM_STAGE + SM_BL);

        uint32_t ah[4][4], al[4][4];
        #pragma unroll
        for (int mi = 0; mi < 4; mi++) {
            int r = wm + mi * 16 + rl;
            ah[mi][0] = *(const uint32_t*)(Ah + r * 24 + kq * 2);
            ah[mi][1] = *(const uint32_t*)(Ah + (r + 8) * 24 + kq * 2);
            ah[mi][2] = *(const uint32_t*)(Ah + r * 24 + kq * 2 + 8);
            ah[mi][3] = *(const uint32_t*)(Ah + (r + 8) * 24 + kq * 2 + 8);
            al[mi][0] = *(const uint32_t*)(Al + r * 24 + kq * 2);
            al[mi][1] = *(const uint32_t*)(Al + (r + 8) * 24 + kq * 2);
            al[mi][2] = *(const uint32_t*)(Al + r * 24 + kq * 2 + 8);
            al[mi][3] = *(const uint32_t*)(Al + (r + 8) * 24 + kq * 2 + 8);
        }

        #pragma unroll
        for (int nh = 0; nh < 2; nh++) {
            uint32_t bh[4][2], bl[4][2];
            #pragma unroll
            for (int nj = 0; nj < 4; nj++) {
                int n = wn + nh * 32 + nj * 8 + rl;
                bh[nj][0] = *(const uint32_t*)(Bh + n * 24 + kq * 2);
                bh[nj][1] = *(const uint32_t*)(Bh + n * 24 + kq * 2 + 8);
                bl[nj][0] = *(const uint32_t*)(Bl + n * 24 + kq * 2);
                bl[nj][1] = *(const uint32_t*)(Bl + n * 24 + kq * 2 + 8);
            }
            #pragma unroll
            for (int mi = 0; mi < 4; mi++)
                #pragma unroll
                for (int nj = 0; nj < 4; nj++) {
                    float* c = acc[mi][nh * 4 + nj];
                    mma16816(c, ah[mi], bh[nj]);
                    mma16816(c, ah[mi], bl[nj]);
                    mma16816(c, al[mi], bh[nj]);
                }
        }
        __syncthreads();
    }

    // ---- epilogue ----
    #pragma unroll
    for (int nn = 0; nn < 8; nn++) {
        int col = wn + nn * 8 + kq * 2;
        float2 bb = make_float2(0.f, 0.f);
        if (ADD_BIAS) bb = *(const float2*)(bias + col);
        #pragma unroll
        for (int mi = 0; mi < 4; mi++) {
            int r = rowBase + wm + mi * 16 + rl;
            if (r < M) {
                float2 v = make_float2(acc[mi][nn][0] + bb.x,
                                       acc[mi][nn][1] + bb.y);
                *(float2*)(C + (size_t)r * HID + col) = v;
            }
            if (r + 8 < M) {
                float2 v = make_float2(acc[mi][nn][2] + bb.x,
                                       acc[mi][nn][3] + bb.y);
                *(float2*)(C + (size_t)(r + 8) * HID + col) = v;
            }
        }
    }
}

// ---------------- gather (aggregate BEFORE transform) ----------------
// y_i = dis_i * ( dis_i*op(in_i) + sum_j dis_j*op(in_j) )
// gather1: width 128, op = identity (input x).
__global__ void __launch_bounds__(256)
gather1_kernel(const float* __restrict__ x, float* __restrict__ y, int M)
{
    const int lane = threadIdx.x & 31;
    int gwarp = (blockIdx.x * blockDim.x + threadIdx.x) >> 5;
    int nwarp = (gridDim.x * blockDim.x) >> 5;

    for (int n = gwarp; n < M; n += nwarp) {
        const float dn = g_dis[n];
        float4 a = __ldg((const float4*)(x + (size_t)n * NFEAT) + lane);
        a.x *= dn; a.y *= dn; a.z *= dn; a.w *= dn;
        const int roff = g_rowoff[n];
        const int dc = g_deg[n];
        int j = 0;
        for (; j + 1 < dc; j += 2) {
            int s0 = __ldg(g_csr + roff + j);
            int s1 = __ldg(g_csr + roff + j + 1);
            float d0 = g_dis[s0], d1 = g_dis[s1];
            float4 b = __ldg((const float4*)(x + (size_t)s0 * NFEAT) + lane);
            float4 c = __ldg((const float4*)(x + (size_t)s1 * NFEAT) + lane);
            a.x += b.x * d0 + c.x * d1; a.y += b.y * d0 + c.y * d1;
            a.z += b.z * d0 + c.z * d1; a.w += b.w * d0 + c.w * d1;
        }
        if (j < dc) {
            int s0 = __ldg(g_csr + roff + j);
            float d0 = g_dis[s0];
            float4 b = __ldg((const float4*)(x + (size_t)s0 * NFEAT) + lane);
            a.x += b.x * d0; a.y += b.y * d0; a.z += b.z * d0; a.w += b.w * d0;
        }
        a.x *= dn; a.y *= dn; a.z *= dn; a.w *= dn;
        *((float4*)(y + (size_t)n * NFEAT) + lane) = a;
    }
}

// gather2: width 256, op = BN affine (g_bns/g_bnt) applied on load.
__global__ void __launch_bounds__(256)
gather2_kernel(const float* __restrict__ h, float* __restrict__ y, int M)
{
    const int lane = threadIdx.x & 31;
    int gwarp = (blockIdx.x * blockDim.x + threadIdx.x) >> 5;
    int nwarp = (gridDim.x * blockDim.x) >> 5;

    const float4 s0 = *(const float4*)(g_bns + lane * 4);
    const float4 t0 = *(const float4*)(g_bnt + lane * 4);
    const float4 s1 = *(const float4*)(g_bns + 128 + lane * 4);
    const float4 t1 = *(const float4*)(g_bnt + 128 + lane * 4);

    for (int n = gwarp; n < M; n += nwarp) {
        const float dn = g_dis[n];
        const float4* sp = (const float4*)(h + (size_t)n * HID);
        float4 v0 = __ldg(sp + lane);
        float4 v1 = __ldg(sp + lane + 32);
        float4 a0, a1;
        a0.x = fmaf(v0.x, s0.x, t0.x) * dn; a0.y = fmaf(v0.y, s0.y, t0.y) * dn;
        a0.z = fmaf(v0.z, s0.z, t0.z) * dn; a0.w = fmaf(v0.w, s0.w, t0.w) * dn;
        a1.x = fmaf(v1.x, s1.x, t1.x) * dn; a1.y = fmaf(v1.y, s1.y, t1.y) * dn;
        a1.z = fmaf(v1.z, s1.z, t1.z) * dn; a1.w = fmaf(v1.w, s1.w, t1.w) * dn;

        const int roff = g_rowoff[n];
        const int dc = g_deg[n];
        for (int j = 0; j < dc; j++) {
            int sj = __ldg(g_csr + roff + j);
            float dj = g_dis[sj];
            const float4* pj = (const float4*)(h + (size_t)sj * HID);
            float4 b0 = __ldg(pj + lane);
            float4 b1 = __ldg(pj + lane + 32);
            a0.x += fmaf(b0.x, s0.x, t0.x) * dj; a0.y += fmaf(b0.y, s0.y, t0.y) * dj;
            a0.z += fmaf(b0.z, s0.z, t0.z) * dj; a0.w += fmaf(b0.w, s0.w, t0.w) * dj;
            a1.x += fmaf(b1.x, s1.x, t1.x) * dj; a1.y += fmaf(b1.y, s1.y, t1.y) * dj;
            a1.z += fmaf(b1.z, s1.z, t1.z) * dj; a1.w += fmaf(b1.w, s1.w, t1.w) * dj;
        }

        a0.x *= dn; a0.y *= dn; a0.z *= dn; a0.w *= dn;
        a1.x *= dn; a1.y *= dn; a1.z *= dn; a1.w *= dn;
        float4* yp = (float4*)(y + (size_t)n * HID);
        yp[lane] = a0;
        yp[lane + 32] = a1;
    }
}

// ---------------- BN statistics: column sums of h ----------------
__global__ void __launch_bounds__(HID)
stats_kernel(const float* __restrict__ h, int M)
{
    const int col = threadIdx.x;
    int r0 = blockIdx.x * 256;
    int r1 = min(r0 + 256, M);
    double s = 0.0, q = 0.0;
    for (int r = r0; r < r1; r++) {
        float v = __ldg(h + (size_t)r * HID + col);
        s += v;
        q += (double)v * (double)v;
    }
    atomicAdd(&g_sum[col], s);
    atomicAdd(&g_sumsq[col], q);
}

__global__ void bn_finalize(const float* __restrict__ gamma,
                            const float* __restrict__ beta, int M)
{
    int c = threadIdx.x;
    double m   = g_sum[c] / (double)M;
    double var = g_sumsq[c] / (double)M - m * m;
    float sc = gamma[c] * rsqrtf((float)var + BN_EPS);
    g_bns[c] = sc;
    g_bnt[c] = beta[c] - (float)m * sc;
    g_sum[c] = 0.0; g_sumsq[c] = 0.0;
}

// ---------------- launch ----------------
extern "C" void kernel_launch(void* const* d_in, const int* in_sizes, int n_in,
                              void* d_out, int out_size)
{
    const float* x   = (const float*)d_in[0];
    const void*  ei  = d_in[1];
    const float* W1  = (const float*)d_in[2];
    const float* g1  = (const float*)d_in[4];
    const float* be1 = (const float*)d_in[5];
    const float* W2  = (const float*)d_in[6];
    const float* g2  = (const float*)d_in[8];
    const float* be2 = (const float*)d_in[9];
    const float* Wfc = (const float*)d_in[10];
    const float* bfc = (const float*)d_in[11];
    float* out = (float*)d_out;

    const int M = in_sizes[0] / NFEAT;   // 50000
    const int E = in_sizes[1] / 2;       // 800000

    void *p_h, *p_y, *p_ahi, *p_alo;
    void *p_w1h, *p_w1l, *p_w2h, *p_w2l, *p_wfh, *p_wfl;
    cudaGetSymbolAddress(&p_h, g_h);
    cudaGetSymbolAddress(&p_y, g_y);
    cudaGetSymbolAddress(&p_ahi, g_ahi);
    cudaGetSymbolAddress(&p_alo, g_alo);
    cudaGetSymbolAddress(&p_w1h, g_w1h);
    cudaGetSymbolAddress(&p_w1l, g_w1l);
    cudaGetSymbolAddress(&p_w2h, g_w2h);
    cudaGetSymbolAddress(&p_w2l, g_w2l);
    cudaGetSymbolAddress(&p_wfh, g_wfh);
    cudaGetSymbolAddress(&p_wfl, g_wfl);
    float* h = (float*)p_h;
    float* y = (float*)p_y;
    bf16 *ahi = (bf16*)p_ahi, *alo = (bf16*)p_alo;

    const int TB = 256;
    const int NB = (M + 255) / 256;
    const int gemmGrid = (M + 127) / 128;
    const int gatherBlocks = 592;
    const int SMEM = 2 * SM_STAGE;   // 73728

    cudaFuncSetAttribute(gemm_mma<NFEAT, false>,
                         cudaFuncAttributeMaxDynamicSharedMemorySize, SMEM);
    cudaFuncSetAttribute(gemm_mma<HID, false>,
                         cudaFuncAttributeMaxDynamicSharedMemorySize, SMEM);
    cudaFuncSetAttribute(gemm_mma<HID, true>,
                         cudaFuncAttributeMaxDynamicSharedMemorySize, SMEM);

    // ---- prep: edge decode + CSR + dis ----
    init_kernel<<<NB, TB>>>(M);
    detect_kernel<<<(E + TB - 1) / TB, TB>>>((const unsigned long long*)ei, E, M);
    convert_kernel<<<(E + TB - 1) / TB, TB>>>(ei, E);
    partsum_kernel<<<NB, 256>>>(M);
    scanpart_kernel<<<1, 256>>>(NB);
    scanfinal_kernel<<<NB, 256>>>(M);
    fill_kernel<<<(E + TB - 1) / TB, TB>>>(E);

    // ---- weight splits (transposed) ----
    wsplit_kernel<<<(NFEAT * HID) / TB, TB>>>(W1, (bf16*)p_w1h, (bf16*)p_w1l, NFEAT);
    wsplit_kernel<<<(HID * HID) / TB, TB>>>(W2, (bf16*)p_w2h, (bf16*)p_w2l, HID);
    wsplit_kernel<<<(HID * HID) / TB, TB>>>(Wfc, (bf16*)p_wfh, (bf16*)p_wfl, HID);

    // ---- layer 1: y0 = A_hat x ; h1 = y0 @ W1 ; BN1 stats ----
    gather1_kernel<<<gatherBlocks, TB>>>(x, y, M);
    split_kernel<false><<<(M * NFEAT / 4 + TB - 1) / TB, TB>>>(y, ahi, alo, M * NFEAT / 4);
    gemm_mma<NFEAT, false><<<gemmGrid, TB, SMEM>>>(ahi, alo, (bf16*)p_w1h, (bf16*)p_w1l, h, M, nullptr);
    stats_kernel<<<NB, HID>>>(h, M);
    bn_finalize<<<1, HID>>>(g1, be1, M);

    // ---- layer 2: y1 = A_hat bn1(h1) ; h2 = y1 @ W2 ; BN2 stats ----
    gather2_kernel<<<gatherBlocks, TB>>>(h, y, M);
    split_kernel<false><<<(M * HID / 4 + TB - 1) / TB, TB>>>(y, ahi, alo, M * HID / 4);
    gemm_mma<HID, false><<<gemmGrid, TB, SMEM>>>(ahi, alo, (bf16*)p_w2h, (bf16*)p_w2l, h, M, nullptr);
    stats_kernel<<<NB, HID>>>(h, M);
    bn_finalize<<<1, HID>>>(g2, be2, M);

    // ---- FC: out = bn2(h2) @ Wfc + bfc ----
    split_kernel<true><<<(M * HID / 4 + TB - 1) / TB, TB>>>(h, ahi, alo, M * HID / 4);
    gemm_mma<HID, true><<<gemmGrid, TB, SMEM>>>(ahi, alo, (bf16*)p_wfh, (bf16*)p_wfl, out, M, bfc);
}

// round 7
// speedup vs baseline: 2.7112x; 1.0111x over previous
#include <cuda_runtime.h>
#include <cuda_bf16.h>
#include <cstdint>

#define N_NODES_MAX 50000
#define N_EDGES_MAX 800000
#define NFEAT 128
#define HID 256
#define BN_EPS 1e-5f

typedef __nv_bfloat16 bf16;

// ---------------- scratch (static __device__, no allocation) ----------------
__device__ float  g_h  [(size_t)N_NODES_MAX * HID];
__device__ float  g_z  [(size_t)N_NODES_MAX * HID];
__device__ bf16   g_ahi[(size_t)N_NODES_MAX * HID];
__device__ bf16   g_alo[(size_t)N_NODES_MAX * HID];
__device__ bf16   g_w1h[HID * NFEAT], g_w1l[HID * NFEAT];     // [N][K] transposed
__device__ bf16   g_w2h[HID * HID],   g_w2l[HID * HID];
__device__ bf16   g_wfh[HID * HID],   g_wfl[HID * HID];
__device__ float  g_dis[N_NODES_MAX];
__device__ int    g_deg[N_NODES_MAX];
__device__ int    g_rowoff[N_NODES_MAX];
__device__ int    g_cursor[N_NODES_MAX];
__device__ int    g_src[N_EDGES_MAX];
__device__ int    g_dst[N_EDGES_MAX];
__device__ int    g_csr[N_EDGES_MAX];
__device__ int    g_part[256];
__device__ int    g_partscan[256];
__device__ int    g_is32;
__device__ double g_sum[HID];
__device__ double g_sumsq[HID];
__device__ float  g_bns[HID];
__device__ float  g_bnt[HID];

// ---------------- prep ----------------
__global__ void init_kernel(int n) {
    int i = blockIdx.x * blockDim.x + threadIdx.x;
    if (i < n) g_deg[i] = 0;
    if (i == 0) g_is32 = 0;
    if (i < HID) { g_sum[i] = 0.0; g_sumsq[i] = 0.0; }
}

__global__ void detect_kernel(const unsigned long long* __restrict__ p,
                              int E, int M) {
    int i = blockIdx.x * blockDim.x + threadIdx.x;
    if (i < E && p[i] >= (unsigned long long)M) g_is32 = 1;
}

__global__ void convert_kernel(const void* __restrict__ ei, int E) {
    int e = blockIdx.x * blockDim.x + threadIdx.x;
    if (e >= E) return;
    int s, d;
    if (g_is32) {
        const int* p = (const int*)ei;
        s = p[e]; d = p[E + e];
    } else {
        const long long* p = (const long long*)ei;
        s = (int)p[e]; d = (int)p[(size_t)E + e];
    }
    g_src[e] = s;
    g_dst[e] = d;
    atomicAdd(&g_deg[d], 1);
}

__global__ void __launch_bounds__(256)
partsum_kernel(int M) {
    __shared__ int sh[8];
    const int tid = threadIdx.x;
    int i = blockIdx.x * 256 + tid;
    int v = (i < M) ? g_deg[i] : 0;
    #pragma unroll
    for (int o = 16; o > 0; o >>= 1) v += __shfl_down_sync(~0u, v, o);
    if ((tid & 31) == 0) sh[tid >> 5] = v;
    __syncthreads();
    if (tid < 8) {
        int w = sh[tid];
        #pragma unroll
        for (int o = 4; o > 0; o >>= 1) w += __shfl_down_sync(0xffu, w, o);
        if (tid == 0) g_part[blockIdx.x] = w;
    }
}

__global__ void __launch_bounds__(256)
scanpart_kernel(int NB) {
    __shared__ int sh[256];
    const int t = threadIdx.x;
    sh[t] = (t < NB) ? g_part[t] : 0;
    __syncthreads();
    for (int off = 1; off < 256; off <<= 1) {
        int v = (t >= off) ? sh[t - off] : 0;
        __syncthreads();
        sh[t] += v;
        __syncthreads();
    }
    if (t < NB) g_partscan[t] = (t == 0) ? 0 : sh[t - 1];
}

__global__ void __launch_bounds__(256)
scanfinal_kernel(int M) {
    __shared__ int sh[8];
    const int tid = threadIdx.x;
    int i = blockIdx.x * 256 + tid;
    int d = (i < M) ? g_deg[i] : 0;
    int v = d;
    #pragma unroll
    for (int o = 1; o < 32; o <<= 1) {
        int u = __shfl_up_sync(~0u, v, o);
        if ((tid & 31) >= o) v += u;
    }
    if ((tid & 31) == 31) sh[tid >> 5] = v;
    __syncthreads();
    if (tid < 8) {
        int w = sh[tid];
        #pragma unroll
        for (int o = 1; o < 8; o <<= 1) {
            int u = __shfl_up_sync(0xffu, w, o);
            if (tid >= o) w += u;
        }
        sh[tid] = w;
    }
    __syncthreads();
    int warpBase = (tid >= 32) ? sh[(tid >> 5) - 1] : 0;
    int excl = g_partscan[blockIdx.x] + warpBase + v - d;
    if (i < M) {
        g_rowoff[i] = excl;
        g_cursor[i] = excl;
        g_dis[i] = rsqrtf((float)(d + 1));
    }
}

__global__ void fill_kernel(int E) {
    int e = blockIdx.x * blockDim.x + threadIdx.x;
    if (e >= E) return;
    int d = g_dst[e];
    int pos = atomicAdd(&g_cursor[d], 1);
    g_csr[pos] = g_src[e];
}

// ---------------- weight split (transposed): wT[n][k] = split(W[k][n]) -----
__global__ void wsplit_kernel(const float* __restrict__ W,
                              bf16* __restrict__ whi, bf16* __restrict__ wlo,
                              int K) {
    int idx = blockIdx.x * blockDim.x + threadIdx.x;
    if (idx >= K * HID) return;
    int k = idx >> 8;
    int n = idx & 255;
    float v = W[idx];
    bf16 h = __float2bfloat16(v);
    bf16 l = __float2bfloat16(v - __bfloat162float(h));
    whi[(size_t)n * K + k] = h;
    wlo[(size_t)n * K + k] = l;
}

// ---------------- split helpers ----------------
__device__ __forceinline__ uint32_t pack2(float a, float b) {
    __nv_bfloat162 t = __floats2bfloat162_rn(a, b);
    return *(uint32_t*)&t;
}

__device__ __forceinline__ void split4(const float4 v, uint2& H, uint2& L) {
    float hx = __bfloat162float(__float2bfloat16(v.x));
    float hy = __bfloat162float(__float2bfloat16(v.y));
    float hz = __bfloat162float(__float2bfloat16(v.z));
    float hw = __bfloat162float(__float2bfloat16(v.w));
    H.x = pack2(v.x, v.y); H.y = pack2(v.z, v.w);
    L.x = pack2(v.x - hx, v.y - hy); L.y = pack2(v.z - hz, v.w - hw);
}

// standalone split with BN affine (FC input path)
__global__ void __launch_bounds__(256)
split_affine_kernel(const float* __restrict__ in, bf16* __restrict__ hi,
                    bf16* __restrict__ lo, int n4) {
    int i = blockIdx.x * blockDim.x + threadIdx.x;
    if (i >= n4) return;
    float4 v = __ldg((const float4*)in + i);
    int c = (i * 4) & 255;
    float4 s = *(const float4*)(g_bns + c);
    float4 t = *(const float4*)(g_bnt + c);
    v.x = fmaf(v.x, s.x, t.x); v.y = fmaf(v.y, s.y, t.y);
    v.z = fmaf(v.z, s.z, t.z); v.w = fmaf(v.w, s.w, t.w);
    uint2 H, L;
    split4(v, H, L);
    *((uint2*)hi + i) = H;
    *((uint2*)lo + i) = L;
}

// z = (h * bns + bnt) * dis[row]   (prepares gather2 input; pure adds there)
__global__ void __launch_bounds__(256)
scale_kernel(const float* __restrict__ h, float* __restrict__ z, int n4) {
    int i = blockIdx.x * blockDim.x + threadIdx.x;
    if (i >= n4) return;
    int row = i >> 6;                 // 64 float4 per 256-wide row
    int c = (i & 63) * 4;
    float4 v = __ldg((const float4*)h + i);
    float4 s = *(const float4*)(g_bns + c);
    float4 t = *(const float4*)(g_bnt + c);
    float d = g_dis[row];
    v.x = fmaf(v.x, s.x, t.x) * d; v.y = fmaf(v.y, s.y, t.y) * d;
    v.z = fmaf(v.z, s.z, t.z) * d; v.w = fmaf(v.w, s.w, t.w) * d;
    *((float4*)z + i) = v;
}

// ---------------- tensor-core GEMM: C[M,256] = A[M,K] @ WT[256,K]^T -------
__device__ __forceinline__ void mma16816(float* c, const uint32_t* a,
                                         const uint32_t* b) {
    asm volatile(
        "mma.sync.aligned.m16n8k16.row.col.f32.bf16.bf16.f32 "
        "{%0,%1,%2,%3}, {%4,%5,%6,%7}, {%8,%9}, {%0,%1,%2,%3};"
        : "+f"(c[0]), "+f"(c[1]), "+f"(c[2]), "+f"(c[3])
        : "r"(a[0]), "r"(a[1]), "r"(a[2]), "r"(a[3]), "r"(b[0]), "r"(b[1]));
}

__device__ __forceinline__ void cpa16(void* s, const void* g) {
    uint32_t sa = (uint32_t)__cvta_generic_to_shared(s);
    asm volatile("cp.async.cg.shared.global [%0], [%1], 16;" :: "r"(sa), "l"(g));
}

#define SM_STAGE 36864
#define SM_AL    6144
#define SM_BH    12288
#define SM_BL    24576

template<int K, bool ADD_BIAS>
__global__ void __launch_bounds__(256)
gemm_mma(const bf16* __restrict__ Ahi, const bf16* __restrict__ Alo,
         const bf16* __restrict__ Bhi, const bf16* __restrict__ Blo,
         float* __restrict__ C, int M, const float* __restrict__ bias)
{
    extern __shared__ char smbuf[];
    constexpr int NK = K / 16;
    const int tid = threadIdx.x;
    const int l   = tid & 31;
    const int wid = tid >> 5;
    const int wm  = (wid & 1) * 64;
    const int wn  = (wid >> 1) * 64;
    const int rowBase = blockIdx.x * 128;

    const int arow  = tid >> 1;
    const int ahalf = tid & 1;
    const int gar   = min(rowBase + arow, M - 1);
    const size_t aoff = (size_t)gar * K + ahalf * 8;
    const int asm_off = arow * 48 + ahalf * 16;

    float acc[4][8][4] = {};

    auto issue = [&](int kt, int buf) {
        char* st = smbuf + buf * SM_STAGE;
        int ko = kt * 16;
        cpa16(st + asm_off,         Ahi + aoff + ko);
        cpa16(st + SM_AL + asm_off, Alo + aoff + ko);
        #pragma unroll
        for (int q = 0; q < 2; q++) {
            int slot = tid + q * 256;
            int n = slot >> 1, hh = slot & 1;
            size_t boff = (size_t)n * K + ko + hh * 8;
            int so = n * 48 + hh * 16;
            cpa16(st + SM_BH + so, Bhi + boff);
            cpa16(st + SM_BL + so, Blo + boff);
        }
    };

    issue(0, 0);
    asm volatile("cp.async.commit_group;");

    const int kq = l & 3;
    const int rl = l >> 2;

    for (int kt = 0; kt < NK; kt++) {
        const int buf = kt & 1;
        if (kt + 1 < NK) {
            issue(kt + 1, buf ^ 1);
            asm volatile("cp.async.commit_group;");
            asm volatile("cp.async.wait_group 1;");
        } else {
            asm volatile("cp.async.wait_group 0;");
        }
        __syncthreads();

        const bf16* Ah = (const bf16*)(smbuf + buf * SM_STAGE);
        const bf16* Al = (const bf16*)(smbuf + buf * SM_STAGE + SM_AL);
        const bf16* Bh = (const bf16*)(smbuf + buf * SM_STAGE + SM_BH);
        const bf16* Bl = (const bf16*)(smbuf + buf * SM_STAGE + SM_BL);

        uint32_t ah[4][4], al[4][4];
        #pragma unroll
        for (int mi = 0; mi < 4; mi++) {
            int r = wm + mi * 16 + rl;
            ah[mi][0] = *(const uint32_t*)(Ah + r * 24 + kq * 2);
            ah[mi][1] = *(const uint32_t*)(Ah + (r + 8) * 24 + kq * 2);
            ah[mi][2] = *(const uint32_t*)(Ah + r * 24 + kq * 2 + 8);
            ah[mi][3] = *(const uint32_t*)(Ah + (r + 8) * 24 + kq * 2 + 8);
            al[mi][0] = *(const uint32_t*)(Al + r * 24 + kq * 2);
            al[mi][1] = *(const uint32_t*)(Al + (r + 8) * 24 + kq * 2);
            al[mi][2] = *(const uint32_t*)(Al + r * 24 + kq * 2 + 8);
            al[mi][3] = *(const uint32_t*)(Al + (r + 8) * 24 + kq * 2 + 8);
        }

        #pragma unroll
        for (int nh = 0; nh < 2; nh++) {
            uint32_t bh[4][2], bl[4][2];
            #pragma unroll
            for (int nj = 0; nj < 4; nj++) {
                int n = wn + nh * 32 + nj * 8 + rl;
                bh[nj][0] = *(const uint32_t*)(Bh + n * 24 + kq * 2);
                bh[nj][1] = *(const uint32_t*)(Bh + n * 24 + kq * 2 + 8);
                bl[nj][0] = *(const uint32_t*)(Bl + n * 24 + kq * 2);
                bl[nj][1] = *(const uint32_t*)(Bl + n * 24 + kq * 2 + 8);
            }
            #pragma unroll
            for (int mi = 0; mi < 4; mi++)
                #pragma unroll
                for (int nj = 0; nj < 4; nj++) {
                    float* c = acc[mi][nh * 4 + nj];
                    mma16816(c, ah[mi], bh[nj]);
                    mma16816(c, ah[mi], bl[nj]);
                    mma16816(c, al[mi], bh[nj]);
                }
        }
        __syncthreads();
    }

    #pragma unroll
    for (int nn = 0; nn < 8; nn++) {
        int col = wn + nn * 8 + kq * 2;
        float2 bb = make_float2(0.f, 0.f);
        if (ADD_BIAS) bb = *(const float2*)(bias + col);
        #pragma unroll
        for (int mi = 0; mi < 4; mi++) {
            int r = rowBase + wm + mi * 16 + rl;
            if (r < M) {
                float2 v = make_float2(acc[mi][nn][0] + bb.x,
                                       acc[mi][nn][1] + bb.y);
                *(float2*)(C + (size_t)r * HID + col) = v;
            }
            if (r + 8 < M) {
                float2 v = make_float2(acc[mi][nn][2] + bb.x,
                                       acc[mi][nn][3] + bb.y);
                *(float2*)(C + (size_t)(r + 8) * HID + col) = v;
            }
        }
    }
}

// ---------------- gather kernels (pure-add inner loops, split fused) -------
// gather1: width 128 input x; out = split( dis_i*(dis_i*x_i + sum dis_j*x_j) )
__global__ void __launch_bounds__(256)
gather1_kernel(const float* __restrict__ x, bf16* __restrict__ hi,
               bf16* __restrict__ lo, int M)
{
    const int lane = threadIdx.x & 31;
    int gwarp = (blockIdx.x * blockDim.x + threadIdx.x) >> 5;
    int nwarp = (gridDim.x * blockDim.x) >> 5;

    for (int n = gwarp; n < M; n += nwarp) {
        const float dn = g_dis[n];
        float4 a = __ldg((const float4*)(x + (size_t)n * NFEAT) + lane);
        a.x *= dn; a.y *= dn; a.z *= dn; a.w *= dn;
        const int roff = g_rowoff[n];
        const int dc = g_deg[n];
        int j = 0;
        for (; j + 1 < dc; j += 2) {
            int s0 = __ldg(g_csr + roff + j);
            int s1 = __ldg(g_csr + roff + j + 1);
            float d0 = g_dis[s0], d1 = g_dis[s1];
            float4 b = __ldg((const float4*)(x + (size_t)s0 * NFEAT) + lane);
            float4 c = __ldg((const float4*)(x + (size_t)s1 * NFEAT) + lane);
            a.x += b.x * d0 + c.x * d1; a.y += b.y * d0 + c.y * d1;
            a.z += b.z * d0 + c.z * d1; a.w += b.w * d0 + c.w * d1;
        }
        if (j < dc) {
            int s0 = __ldg(g_csr + roff + j);
            float d0 = g_dis[s0];
            float4 b = __ldg((const float4*)(x + (size_t)s0 * NFEAT) + lane);
            a.x += b.x * d0; a.y += b.y * d0; a.z += b.z * d0; a.w += b.w * d0;
        }
        a.x *= dn; a.y *= dn; a.z *= dn; a.w *= dn;
        uint2 H, L;
        split4(a, H, L);
        *((uint2*)(hi + (size_t)n * NFEAT) + lane) = H;
        *((uint2*)(lo + (size_t)n * NFEAT) + lane) = L;
    }
}

// gather2: width 256 input z (pre-scaled); out = split( dis_i*(z_i + sum z_j) )
__global__ void __launch_bounds__(256)
gather2_kernel(const float* __restrict__ z, bf16* __restrict__ hi,
               bf16* __restrict__ lo, int M)
{
    const int lane = threadIdx.x & 31;
    int gwarp = (blockIdx.x * blockDim.x + threadIdx.x) >> 5;
    int nwarp = (gridDim.x * blockDim.x) >> 5;

    for (int n = gwarp; n < M; n += nwarp) {
        const float4* sp = (const float4*)(z + (size_t)n * HID);
        float4 a0 = __ldg(sp + lane);
        float4 a1 = __ldg(sp + lane + 32);

        const int roff = g_rowoff[n];
        const int dc = g_deg[n];
        int j = 0;
        for (; j + 1 < dc; j += 2) {
            int s0 = __ldg(g_csr + roff + j);
            int s1 = __ldg(g_csr + roff + j + 1);
            const float4* p0 = (const float4*)(z + (size_t)s0 * HID);
            const float4* p1 = (const float4*)(z + (size_t)s1 * HID);
            float4 b0 = __ldg(p0 + lane);
            float4 b1 = __ldg(p0 + lane + 32);
            float4 c0 = __ldg(p1 + lane);
            float4 c1 = __ldg(p1 + lane + 32);
            a0.x += b0.x + c0.x; a0.y += b0.y + c0.y;
            a0.z += b0.z + c0.z; a0.w += b0.w + c0.w;
            a1.x += b1.x + c1.x; a1.y += b1.y + c1.y;
            a1.z += b1.z + c1.z; a1.w += b1.w + c1.w;
        }
        if (j < dc) {
            int s0 = __ldg(g_csr + roff + j);
            const float4* p0 = (const float4*)(z + (size_t)s0 * HID);
            float4 b0 = __ldg(p0 + lane);
            float4 b1 = __ldg(p0 + lane + 32);
            a0.x += b0.x; a0.y += b0.y; a0.z += b0.z; a0.w += b0.w;
            a1.x += b1.x; a1.y += b1.y; a1.z += b1.z; a1.w += b1.w;
        }

        const float dn = g_dis[n];
        a0.x *= dn; a0.y *= dn; a0.z *= dn; a0.w *= dn;
        a1.x *= dn; a1.y *= dn; a1.z *= dn; a1.w *= dn;

        uint2 H0, L0, H1, L1;
        split4(a0, H0, L0);
        split4(a1, H1, L1);
        *((uint2*)(hi + (size_t)n * HID) + lane) = H0;
        *((uint2*)(hi + (size_t)n * HID) + lane + 32) = H1;
        *((uint2*)(lo + (size_t)n * HID) + lane) = L0;
        *((uint2*)(lo + (size_t)n * HID) + lane + 32) = L1;
    }
}

// ---------------- BN statistics: column sums of h ----------------
__global__ void __launch_bounds__(HID)
stats_kernel(const float* __restrict__ h, int M)
{
    const int col = threadIdx.x;
    int r0 = blockIdx.x * 256;
    int r1 = min(r0 + 256, M);
    double s = 0.0, q = 0.0;
    for (int r = r0; r < r1; r++) {
        float v = __ldg(h + (size_t)r * HID + col);
        s += v;
        q += (double)v * (double)v;
    }
    atomicAdd(&g_sum[col], s);
    atomicAdd(&g_sumsq[col], q);
}

__global__ void bn_finalize(const float* __restrict__ gamma,
                            const float* __restrict__ beta, int M)
{
    int c = threadIdx.x;
    double m   = g_sum[c] / (double)M;
    double var = g_sumsq[c] / (double)M - m * m;
    float sc = gamma[c] * rsqrtf((float)var + BN_EPS);
    g_bns[c] = sc;
    g_bnt[c] = beta[c] - (float)m * sc;
    g_sum[c] = 0.0; g_sumsq[c] = 0.0;
}

// ---------------- launch ----------------
extern "C" void kernel_launch(void* const* d_in, const int* in_sizes, int n_in,
                              void* d_out, int out_size)
{
    const float* x   = (const float*)d_in[0];
    const void*  ei  = d_in[1];
    const float* W1  = (const float*)d_in[2];
    const float* g1  = (const float*)d_in[4];
    const float* be1 = (const float*)d_in[5];
    const float* W2  = (const float*)d_in[6];
    const float* g2  = (const float*)d_in[8];
    const float* be2 = (const float*)d_in[9];
    const float* Wfc = (const float*)d_in[10];
    const float* bfc = (const float*)d_in[11];
    float* out = (float*)d_out;

    const int M = in_sizes[0] / NFEAT;   // 50000
    const int E = in_sizes[1] / 2;       // 800000

    void *p_h, *p_z, *p_ahi, *p_alo;
    void *p_w1h, *p_w1l, *p_w2h, *p_w2l, *p_wfh, *p_wfl;
    cudaGetSymbolAddress(&p_h, g_h);
    cudaGetSymbolAddress(&p_z, g_z);
    cudaGetSymbolAddress(&p_ahi, g_ahi);
    cudaGetSymbolAddress(&p_alo, g_alo);
    cudaGetSymbolAddress(&p_w1h, g_w1h);
    cudaGetSymbolAddress(&p_w1l, g_w1l);
    cudaGetSymbolAddress(&p_w2h, g_w2h);
    cudaGetSymbolAddress(&p_w2l, g_w2l);
    cudaGetSymbolAddress(&p_wfh, g_wfh);
    cudaGetSymbolAddress(&p_wfl, g_wfl);
    float* h = (float*)p_h;
    float* z = (float*)p_z;
    bf16 *ahi = (bf16*)p_ahi, *alo = (bf16*)p_alo;

    const int TB = 256;
    const int NB = (M + 255) / 256;
    const int gemmGrid = (M + 127) / 128;
    const int gatherBlocks = 592;
    const int SMEM = 2 * SM_STAGE;

    cudaFuncSetAttribute(gemm_mma<NFEAT, false>,
                         cudaFuncAttributeMaxDynamicSharedMemorySize, SMEM);
    cudaFuncSetAttribute(gemm_mma<HID, false>,
                         cudaFuncAttributeMaxDynamicSharedMemorySize, SMEM);
    cudaFuncSetAttribute(gemm_mma<HID, true>,
                         cudaFuncAttributeMaxDynamicSharedMemorySize, SMEM);

    // ---- prep: edge decode + CSR + dis ----
    init_kernel<<<NB, TB>>>(M);
    detect_kernel<<<(E + TB - 1) / TB, TB>>>((const unsigned long long*)ei, E, M);
    convert_kernel<<<(E + TB - 1) / TB, TB>>>(ei, E);
    partsum_kernel<<<NB, 256>>>(M);
    scanpart_kernel<<<1, 256>>>(NB);
    scanfinal_kernel<<<NB, 256>>>(M);
    fill_kernel<<<(E + TB - 1) / TB, TB>>>(E);

    // ---- weight splits (transposed) ----
    wsplit_kernel<<<(NFEAT * HID) / TB, TB>>>(W1, (bf16*)p_w1h, (bf16*)p_w1l, NFEAT);
    wsplit_kernel<<<(HID * HID) / TB, TB>>>(W2, (bf16*)p_w2h, (bf16*)p_w2l, HID);
    wsplit_kernel<<<(HID * HID) / TB, TB>>>(Wfc, (bf16*)p_wfh, (bf16*)p_wfl, HID);

    // ---- layer 1: a = split(A_hat x) ; h1 = a @ W1 ; BN1 stats ----
    gather1_kernel<<<gatherBlocks, TB>>>(x, ahi, alo, M);
    gemm_mma<NFEAT, false><<<gemmGrid, TB, SMEM>>>(ahi, alo, (bf16*)p_w1h, (bf16*)p_w1l, h, M, nullptr);
    stats_kernel<<<NB, HID>>>(h, M);
    bn_finalize<<<1, HID>>>(g1, be1, M);

    // ---- layer 2: z = dis*bn1(h1) ; a = split(A_hat-combine z) ; h2 = a @ W2 ----
    scale_kernel<<<(M * HID / 4 + TB - 1) / TB, TB>>>(h, z, M * HID / 4);
    gather2_kernel<<<gatherBlocks, TB>>>(z, ahi, alo, M);
    gemm_mma<HID, false><<<gemmGrid, TB, SMEM>>>(ahi, alo, (bf16*)p_w2h, (bf16*)p_w2l, h, M, nullptr);
    stats_kernel<<<NB, HID>>>(h, M);
    bn_finalize<<<1, HID>>>(g2, be2, M);

    // ---- FC: out = bn2(h2) @ Wfc + bfc ----
    split_affine_kernel<<<(M * HID / 4 + TB - 1) / TB, TB>>>(h, ahi, alo, M * HID / 4);
    gemm_mma<HID, true><<<gemmGrid, TB, SMEM>>>(ahi, alo, (bf16*)p_wfh, (bf16*)p_wfl, out, M, bfc);
}

// round 9
// speedup vs baseline: 4.2670x; 1.5739x over previous
#include <cuda_runtime.h>
#include <cuda_bf16.h>
#include <cstdint>

#define N_NODES_MAX 50000
#define N_EDGES_MAX 800000
#define NFEAT 128
#define HID 256
#define BN_EPS 1e-5f

typedef __nv_bfloat16 bf16;

// ---------------- scratch (static __device__, no allocation) ----------------
__device__ float  g_h  [(size_t)N_NODES_MAX * HID];
__device__ float  g_z  [(size_t)N_NODES_MAX * HID];
__device__ bf16   g_ahi[(size_t)N_NODES_MAX * HID];
__device__ bf16   g_alo[(size_t)N_NODES_MAX * HID];
__device__ bf16   g_w1h[HID * NFEAT], g_w1l[HID * NFEAT];     // [N][K] transposed
__device__ bf16   g_w2h[HID * HID],   g_w2l[HID * HID];
__device__ bf16   g_wfh[HID * HID],   g_wfl[HID * HID];
__device__ float  g_dis[N_NODES_MAX];
__device__ int    g_deg[N_NODES_MAX];
__device__ int    g_rowoff[N_NODES_MAX];
__device__ int    g_cursor[N_NODES_MAX];
__device__ int    g_src[N_EDGES_MAX];
__device__ int    g_dst[N_EDGES_MAX];
__device__ int    g_csr[N_EDGES_MAX];
__device__ int    g_part[256];
__device__ int    g_partscan[256];
__device__ int    g_is32;
__device__ double g_sum[HID];
__device__ double g_sumsq[HID];
__device__ float  g_bns[HID];
__device__ float  g_bnt[HID];

// ---------------- prep ----------------
__global__ void init_kernel(int n) {
    int i = blockIdx.x * blockDim.x + threadIdx.x;
    if (i < n) g_deg[i] = 0;
    if (i == 0) g_is32 = 0;
    if (i < HID) { g_sum[i] = 0.0; g_sumsq[i] = 0.0; }
}

// Sample-scan the first <=8192 64-bit words. Genuine int64 indices < M;
// packed int32 pairs are >= 2^32 almost surely. Ballot -> 1 store/warp max.
__global__ void detect_kernel(const unsigned long long* __restrict__ p,
                              int Escan, int M) {
    int i = blockIdx.x * blockDim.x + threadIdx.x;
    bool bad = (i < Escan) && (p[i] >= (unsigned long long)M);
    unsigned b = __ballot_sync(~0u, bad);
    if (b && (threadIdx.x & 31) == 0) g_is32 = 1;
}

__global__ void convert_kernel(const void* __restrict__ ei, int E) {
    int e = blockIdx.x * blockDim.x + threadIdx.x;
    if (e >= E) return;
    int s, d;
    if (g_is32) {
        const int* p = (const int*)ei;
        s = p[e]; d = p[E + e];
    } else {
        const long long* p = (const long long*)ei;
        s = (int)p[e]; d = (int)p[(size_t)E + e];
    }
    g_src[e] = s;
    g_dst[e] = d;
    atomicAdd(&g_deg[d], 1);
}

__global__ void __launch_bounds__(256)
partsum_kernel(int M) {
    __shared__ int sh[8];
    const int tid = threadIdx.x;
    int i = blockIdx.x * 256 + tid;
    int v = (i < M) ? g_deg[i] : 0;
    #pragma unroll
    for (int o = 16; o > 0; o >>= 1) v += __shfl_down_sync(~0u, v, o);
    if ((tid & 31) == 0) sh[tid >> 5] = v;
    __syncthreads();
    if (tid < 8) {
        int w = sh[tid];
        #pragma unroll
        for (int o = 4; o > 0; o >>= 1) w += __shfl_down_sync(0xffu, w, o);
        if (tid == 0) g_part[blockIdx.x] = w;
    }
}

__global__ void __launch_bounds__(256)
scanpart_kernel(int NB) {
    __shared__ int sh[256];
    const int t = threadIdx.x;
    sh[t] = (t < NB) ? g_part[t] : 0;
    __syncthreads();
    for (int off = 1; off < 256; off <<= 1) {
        int v = (t >= off) ? sh[t - off] : 0;
        __syncthreads();
        sh[t] += v;
        __syncthreads();
    }
    if (t < NB) g_partscan[t] = (t == 0) ? 0 : sh[t - 1];
}

__global__ void __launch_bounds__(256)
scanfinal_kernel(int M) {
    __shared__ int sh[8];
    const int tid = threadIdx.x;
    int i = blockIdx.x * 256 + tid;
    int d = (i < M) ? g_deg[i] : 0;
    int v = d;
    #pragma unroll
    for (int o = 1; o < 32; o <<= 1) {
        int u = __shfl_up_sync(~0u, v, o);
        if ((tid & 31) >= o) v += u;
    }
    if ((tid & 31) == 31) sh[tid >> 5] = v;
    __syncthreads();
    if (tid < 8) {
        int w = sh[tid];
        #pragma unroll
        for (int o = 1; o < 8; o <<= 1) {
            int u = __shfl_up_sync(0xffu, w, o);
            if (tid >= o) w += u;
        }
        sh[tid] = w;
    }
    __syncthreads();
    int warpBase = (tid >= 32) ? sh[(tid >> 5) - 1] : 0;
    int excl = g_partscan[blockIdx.x] + warpBase + v - d;
    if (i < M) {
        g_rowoff[i] = excl;
        g_cursor[i] = excl;
        g_dis[i] = rsqrtf((float)(d + 1));
    }
}

__global__ void fill_kernel(int E) {
    int e = blockIdx.x * blockDim.x + threadIdx.x;
    if (e >= E) return;
    int d = g_dst[e];
    int pos = atomicAdd(&g_cursor[d], 1);
    g_csr[pos] = g_src[e];
}

// ---------------- all weight splits in ONE kernel (transposed) ----------------
__global__ void wsplit_all(const float* __restrict__ W1,
                           const float* __restrict__ W2,
                           const float* __restrict__ Wfc) {
    int idx = blockIdx.x * blockDim.x + threadIdx.x;
    const float* W; bf16 *hip, *lop; int K; int off;
    const int S1 = NFEAT * HID, S2 = S1 + HID * HID, S3 = S2 + HID * HID;
    if (idx < S1)      { W = W1;  hip = g_w1h; lop = g_w1l; K = NFEAT; off = idx; }
    else if (idx < S2) { W = W2;  hip = g_w2h; lop = g_w2l; K = HID;   off = idx - S1; }
    else if (idx < S3) { W = Wfc; hip = g_wfh; lop = g_wfl; K = HID;   off = idx - S2; }
    else return;
    int k = off >> 8;
    int n = off & 255;
    float v = W[off];
    bf16 h = __float2bfloat16(v);
    bf16 l = __float2bfloat16(v - __bfloat162float(h));
    hip[(size_t)n * K + k] = h;
    lop[(size_t)n * K + k] = l;
}

// ---------------- split helpers ----------------
__device__ __forceinline__ uint32_t pack2(float a, float b) {
    __nv_bfloat162 t = __floats2bfloat162_rn(a, b);
    return *(uint32_t*)&t;
}

__device__ __forceinline__ void split4(const float4 v, uint2& H, uint2& L) {
    float hx = __bfloat162float(__float2bfloat16(v.x));
    float hy = __bfloat162float(__float2bfloat16(v.y));
    float hz = __bfloat162float(__float2bfloat16(v.z));
    float hw = __bfloat162float(__float2bfloat16(v.w));
    H.x = pack2(v.x, v.y); H.y = pack2(v.z, v.w);
    L.x = pack2(v.x - hx, v.y - hy); L.y = pack2(v.z - hz, v.w - hw);
}

__global__ void __launch_bounds__(256)
split_affine_kernel(const float* __restrict__ in, bf16* __restrict__ hi,
                    bf16* __restrict__ lo, int n4) {
    int i = blockIdx.x * blockDim.x + threadIdx.x;
    if (i >= n4) return;
    float4 v = __ldg((const float4*)in + i);
    int c = (i * 4) & 255;
    float4 s = *(const float4*)(g_bns + c);
    float4 t = *(const float4*)(g_bnt + c);
    v.x = fmaf(v.x, s.x, t.x); v.y = fmaf(v.y, s.y, t.y);
    v.z = fmaf(v.z, s.z, t.z); v.w = fmaf(v.w, s.w, t.w);
    uint2 H, L;
    split4(v, H, L);
    *((uint2*)hi + i) = H;
    *((uint2*)lo + i) = L;
}

// z = (h * bns + bnt) * dis[row]
__global__ void __launch_bounds__(256)
scale_kernel(const float* __restrict__ h, float* __restrict__ z, int n4) {
    int i = blockIdx.x * blockDim.x + threadIdx.x;
    if (i >= n4) return;
    int row = i >> 6;
    int c = (i & 63) * 4;
    float4 v = __ldg((const float4*)h + i);
    float4 s = *(const float4*)(g_bns + c);
    float4 t = *(const float4*)(g_bnt + c);
    float d = g_dis[row];
    v.x = fmaf(v.x, s.x, t.x) * d; v.y = fmaf(v.y, s.y, t.y) * d;
    v.z = fmaf(v.z, s.z, t.z) * d; v.w = fmaf(v.w, s.w, t.w) * d;
    *((float4*)z + i) = v;
}

// ---------------- tensor-core GEMM with fused BN stats ----------------
__device__ __forceinline__ void mma16816(float* c, const uint32_t* a,
                                         const uint32_t* b) {
    asm volatile(
        "mma.sync.aligned.m16n8k16.row.col.f32.bf16.bf16.f32 "
        "{%0,%1,%2,%3}, {%4,%5,%6,%7}, {%8,%9}, {%0,%1,%2,%3};"
        : "+f"(c[0]), "+f"(c[1]), "+f"(c[2]), "+f"(c[3])
        : "r"(a[0]), "r"(a[1]), "r"(a[2]), "r"(a[3]), "r"(b[0]), "r"(b[1]));
}

__device__ __forceinline__ void cpa16(void* s, const void* g) {
    uint32_t sa = (uint32_t)__cvta_generic_to_shared(s);
    asm volatile("cp.async.cg.shared.global [%0], [%1], 16;" :: "r"(sa), "l"(g));
}

#define SM_STAGE 36864
#define SM_AL    6144
#define SM_BH    12288
#define SM_BL    24576

template<int K, bool ADD_BIAS, bool STATS>
__global__ void __launch_bounds__(256)
gemm_mma(const bf16* __restrict__ Ahi, const bf16* __restrict__ Alo,
         const bf16* __restrict__ Bhi, const bf16* __restrict__ Blo,
         float* __restrict__ C, int M, const float* __restrict__ bias)
{
    extern __shared__ char smbuf[];
    __shared__ float s_sum[HID], s_sq[HID];
    constexpr int NK = K / 16;
    const int tid = threadIdx.x;
    const int l   = tid & 31;
    const int wid = tid >> 5;
    const int wm  = (wid & 1) * 64;
    const int wn  = (wid >> 1) * 64;
    const int rowBase = blockIdx.x * 128;

    const int arow  = tid >> 1;
    const int ahalf = tid & 1;
    const int gar   = min(rowBase + arow, M - 1);
    const size_t aoff = (size_t)gar * K + ahalf * 8;
    const int asm_off = arow * 48 + ahalf * 16;

    if (STATS) { s_sum[tid] = 0.f; s_sq[tid] = 0.f; }

    float acc[4][8][4] = {};

    auto issue = [&](int kt, int buf) {
        char* st = smbuf + buf * SM_STAGE;
        int ko = kt * 16;
        cpa16(st + asm_off,         Ahi + aoff + ko);
        cpa16(st + SM_AL + asm_off, Alo + aoff + ko);
        #pragma unroll
        for (int q = 0; q < 2; q++) {
            int slot = tid + q * 256;
            int n = slot >> 1, hh = slot & 1;
            size_t boff = (size_t)n * K + ko + hh * 8;
            int so = n * 48 + hh * 16;
            cpa16(st + SM_BH + so, Bhi + boff);
            cpa16(st + SM_BL + so, Blo + boff);
        }
    };

    issue(0, 0);
    asm volatile("cp.async.commit_group;");

    const int kq = l & 3;
    const int rl = l >> 2;

    for (int kt = 0; kt < NK; kt++) {
        const int buf = kt & 1;
        if (kt + 1 < NK) {
            issue(kt + 1, buf ^ 1);
            asm volatile("cp.async.commit_group;");
            asm volatile("cp.async.wait_group 1;");
        } else {
            asm volatile("cp.async.wait_group 0;");
        }
        __syncthreads();

        const bf16* Ah = (const bf16*)(smbuf + buf * SM_STAGE);
        const bf16* Al = (const bf16*)(smbuf + buf * SM_STAGE + SM_AL);
        const bf16* Bh = (const bf16*)(smbuf + buf * SM_STAGE + SM_BH);
        const bf16* Bl = (const bf16*)(smbuf + buf * SM_STAGE + SM_BL);

        uint32_t ah[4][4], al[4][4];
        #pragma unroll
        for (int mi = 0; mi < 4; mi++) {
            int r = wm + mi * 16 + rl;
            ah[mi][0] = *(const uint32_t*)(Ah + r * 24 + kq * 2);
            ah[mi][1] = *(const uint32_t*)(Ah + (r + 8) * 24 + kq * 2);
            ah[mi][2] = *(const uint32_t*)(Ah + r * 24 + kq * 2 + 8);
            ah[mi][3] = *(const uint32_t*)(Ah + (r + 8) * 24 + kq * 2 + 8);
            al[mi][0] = *(const uint32_t*)(Al + r * 24 + kq * 2);
            al[mi][1] = *(const uint32_t*)(Al + (r + 8) * 24 + kq * 2);
            al[mi][2] = *(const uint32_t*)(Al + r * 24 + kq * 2 + 8);
            al[mi][3] = *(const uint32_t*)(Al + (r + 8) * 24 + kq * 2 + 8);
        }

        #pragma unroll
        for (int nh = 0; nh < 2; nh++) {
            uint32_t bh[4][2], bl[4][2];
            #pragma unroll
            for (int nj = 0; nj < 4; nj++) {
                int n = wn + nh * 32 + nj * 8 + rl;
                bh[nj][0] = *(const uint32_t*)(Bh + n * 24 + kq * 2);
                bh[nj][1] = *(const uint32_t*)(Bh + n * 24 + kq * 2 + 8);
                bl[nj][0] = *(const uint32_t*)(Bl + n * 24 + kq * 2);
                bl[nj][1] = *(const uint32_t*)(Bl + n * 24 + kq * 2 + 8);
            }
            #pragma unroll
            for (int mi = 0; mi < 4; mi++)
                #pragma unroll
                for (int nj = 0; nj < 4; nj++) {
                    float* c = acc[mi][nh * 4 + nj];
                    mma16816(c, ah[mi], bh[nj]);
                    mma16816(c, ah[mi], bl[nj]);
                    mma16816(c, al[mi], bh[nj]);
                }
        }
        __syncthreads();
    }

    // ---- epilogue: store + optional fused column stats ----
    #pragma unroll
    for (int nn = 0; nn < 8; nn++) {
        int col = wn + nn * 8 + kq * 2;
        float2 bb = make_float2(0.f, 0.f);
        if (ADD_BIAS) bb = *(const float2*)(bias + col);
        #pragma unroll
        for (int mi = 0; mi < 4; mi++) {
            int r = rowBase + wm + mi * 16 + rl;
            if (r < M) {
                float2 v = make_float2(acc[mi][nn][0] + bb.x,
                                       acc[mi][nn][1] + bb.y);
                *(float2*)(C + (size_t)r * HID + col) = v;
            }
            if (r + 8 < M) {
                float2 v = make_float2(acc[mi][nn][2] + bb.x,
                                       acc[mi][nn][3] + bb.y);
                *(float2*)(C + (size_t)(r + 8) * HID + col) = v;
            }
        }
    }

    if (STATS) {
        #pragma unroll
        for (int nn = 0; nn < 8; nn++) {
            float s0 = 0.f, q0 = 0.f, s1 = 0.f, q1 = 0.f;
            #pragma unroll
            for (int mi = 0; mi < 4; mi++) {
                int r = rowBase + wm + mi * 16 + rl;
                if (r < M) {
                    float v0 = acc[mi][nn][0], v1 = acc[mi][nn][1];
                    s0 += v0; q0 += v0 * v0; s1 += v1; q1 += v1 * v1;
                }
                if (r + 8 < M) {
                    float v0 = acc[mi][nn][2], v1 = acc[mi][nn][3];
                    s0 += v0; q0 += v0 * v0; s1 += v1; q1 += v1 * v1;
                }
            }
            #pragma unroll
            for (int o = 16; o >= 4; o >>= 1) {
                s0 += __shfl_down_sync(~0u, s0, o);
                q0 += __shfl_down_sync(~0u, q0, o);
                s1 += __shfl_down_sync(~0u, s1, o);
                q1 += __shfl_down_sync(~0u, q1, o);
            }
            if (l < 4) {
                int col = wn + nn * 8 + kq * 2;
                atomicAdd(&s_sum[col], s0);     atomicAdd(&s_sq[col], q0);
                atomicAdd(&s_sum[col + 1], s1); atomicAdd(&s_sq[col + 1], q1);
            }
        }
        __syncthreads();
        atomicAdd(&g_sum[tid],   (double)s_sum[tid]);
        atomicAdd(&g_sumsq[tid], (double)s_sq[tid]);
    }
}

// ---------------- gather kernels (pure-add inner loops, split fused) -------
__global__ void __launch_bounds__(256)
gather1_kernel(const float* __restrict__ x, bf16* __restrict__ hi,
               bf16* __restrict__ lo, int M)
{
    const int lane = threadIdx.x & 31;
    int gwarp = (blockIdx.x * blockDim.x + threadIdx.x) >> 5;
    int nwarp = (gridDim.x * blockDim.x) >> 5;

    for (int n = gwarp; n < M; n += nwarp) {
        const float dn = g_dis[n];
        float4 a = __ldg((const float4*)(x + (size_t)n * NFEAT) + lane);
        a.x *= dn; a.y *= dn; a.z *= dn; a.w *= dn;
        const int roff = g_rowoff[n];
        const int dc = g_deg[n];
        int j = 0;
        for (; j + 1 < dc; j += 2) {
            int s0 = __ldg(g_csr + roff + j);
            int s1 = __ldg(g_csr + roff + j + 1);
            float d0 = g_dis[s0], d1 = g_dis[s1];
            float4 b = __ldg((const float4*)(x + (size_t)s0 * NFEAT) + lane);
            float4 c = __ldg((const float4*)(x + (size_t)s1 * NFEAT) + lane);
            a.x += b.x * d0 + c.x * d1; a.y += b.y * d0 + c.y * d1;
            a.z += b.z * d0 + c.z * d1; a.w += b.w * d0 + c.w * d1;
        }
        if (j < dc) {
            int s0 = __ldg(g_csr + roff + j);
            float d0 = g_dis[s0];
            float4 b = __ldg((const float4*)(x + (size_t)s0 * NFEAT) + lane);
            a.x += b.x * d0; a.y += b.y * d0; a.z += b.z * d0; a.w += b.w * d0;
        }
        a.x *= dn; a.y *= dn; a.z *= dn; a.w *= dn;
        uint2 H, L;
        split4(a, H, L);
        *((uint2*)(hi + (size_t)n * NFEAT) + lane) = H;
        *((uint2*)(lo + (size_t)n * NFEAT) + lane) = L;
    }
}

__global__ void __launch_bounds__(256)
gather2_kernel(const float* __restrict__ z, bf16* __restrict__ hi,
               bf16* __restrict__ lo, int M)
{
    const int lane = threadIdx.x & 31;
    int gwarp = (blockIdx.x * blockDim.x + threadIdx.x) >> 5;
    int nwarp = (gridDim.x * blockDim.x) >> 5;

    for (int n = gwarp; n < M; n += nwarp) {
        const float4* sp = (const float4*)(z + (size_t)n * HID);
        float4 a0 = __ldg(sp + lane);
        float4 a1 = __ldg(sp + lane + 32);

        const int roff = g_rowoff[n];
        const int dc = g_deg[n];
        int j = 0;
        for (; j + 1 < dc; j += 2) {
            int s0 = __ldg(g_csr + roff + j);
            int s1 = __ldg(g_csr + roff + j + 1);
            const float4* p0 = (const float4*)(z + (size_t)s0 * HID);
            const float4* p1 = (const float4*)(z + (size_t)s1 * HID);
            float4 b0 = __ldg(p0 + lane);
            float4 b1 = __ldg(p0 + lane + 32);
            float4 c0 = __ldg(p1 + lane);
            float4 c1 = __ldg(p1 + lane + 32);
            a0.x += b0.x + c0.x; a0.y += b0.y + c0.y;
            a0.z += b0.z + c0.z; a0.w += b0.w + c0.w;
            a1.x += b1.x + c1.x; a1.y += b1.y + c1.y;
            a1.z += b1.z + c1.z; a1.w += b1.w + c1.w;
        }
        if (j < dc) {
            int s0 = __ldg(g_csr + roff + j);
            const float4* p0 = (const float4*)(z + (size_t)s0 * HID);
            float4 b0 = __ldg(p0 + lane);
            float4 b1 = __ldg(p0 + lane + 32);
            a0.x += b0.x; a0.y += b0.y; a0.z += b0.z; a0.w += b0.w;
            a1.x += b1.x; a1.y += b1.y; a1.z += b1.z; a1.w += b1.w;
        }

        const float dn = g_dis[n];
        a0.x *= dn; a0.y *= dn; a0.z *= dn; a0.w *= dn;
        a1.x *= dn; a1.y *= dn; a1.z *= dn; a1.w *= dn;

        uint2 H0, L0, H1, L1;
        split4(a0, H0, L0);
        split4(a1, H1, L1);
        *((uint2*)(hi + (size_t)n * HID) + lane) = H0;
        *((uint2*)(hi + (size_t)n * HID) + lane + 32) = H1;
        *((uint2*)(lo + (size_t)n * HID) + lane) = L0;
        *((uint2*)(lo + (size_t)n * HID) + lane + 32) = L1;
    }
}

__global__ void bn_finalize(const float* __restrict__ gamma,
                            const float* __restrict__ beta, int M)
{
    int c = threadIdx.x;
    double m   = g_sum[c] / (double)M;
    double var = g_sumsq[c] / (double)M - m * m;
    float sc = gamma[c] * rsqrtf((float)var + BN_EPS);
    g_bns[c] = sc;
    g_bnt[c] = beta[c] - (float)m * sc;
    g_sum[c] = 0.0; g_sumsq[c] = 0.0;
}

// ---------------- launch ----------------
extern "C" void kernel_launch(void* const* d_in, const int* in_sizes, int n_in,
                              void* d_out, int out_size)
{
    const float* x   = (const float*)d_in[0];
    const void*  ei  = d_in[1];
    const float* W1  = (const float*)d_in[2];
    const float* g1  = (const float*)d_in[4];
    const float* be1 = (const float*)d_in[5];
    const float* W2  = (const float*)d_in[6];
    const float* g2  = (const float*)d_in[8];
    const float* be2 = (const float*)d_in[9];
    const float* Wfc = (const float*)d_in[10];
    const float* bfc = (const float*)d_in[11];
    float* out = (float*)d_out;

    const int M = in_sizes[0] / NFEAT;   // 50000
    const int E = in_sizes[1] / 2;       // 800000

    void *p_h, *p_z, *p_ahi, *p_alo;
    void *p_w1h, *p_w1l, *p_w2h, *p_w2l, *p_wfh, *p_wfl;
    cudaGetSymbolAddress(&p_h, g_h);
    cudaGetSymbolAddress(&p_z, g_z);
    cudaGetSymbolAddress(&p_ahi, g_ahi);
    cudaGetSymbolAddress(&p_alo, g_alo);
    cudaGetSymbolAddress(&p_w1h, g_w1h);
    cudaGetSymbolAddress(&p_w1l, g_w1l);
    cudaGetSymbolAddress(&p_w2h, g_w2h);
    cudaGetSymbolAddress(&p_w2l, g_w2l);
    cudaGetSymbolAddress(&p_wfh, g_wfh);
    cudaGetSymbolAddress(&p_wfl, g_wfl);
    float* h = (float*)p_h;
    float* z = (float*)p_z;
    bf16 *ahi = (bf16*)p_ahi, *alo = (bf16*)p_alo;

    const int TB = 256;
    const int NB = (M + 255) / 256;
    const int gemmGrid = (M + 127) / 128;
    const int gatherBlocks = 592;
    const int SMEM = 2 * SM_STAGE;
    const int Escan = (E < 8192) ? E : 8192;
    const int WSPLIT_N = NFEAT * HID + 2 * HID * HID;

    cudaFuncSetAttribute(gemm_mma<NFEAT, false, true>,
                         cudaFuncAttributeMaxDynamicSharedMemorySize, SMEM);
    cudaFuncSetAttribute(gemm_mma<HID, false, true>,
                         cudaFuncAttributeMaxDynamicSharedMemorySize, SMEM);
    cudaFuncSetAttribute(gemm_mma<HID, true, false>,
                         cudaFuncAttributeMaxDynamicSharedMemorySize, SMEM);

    // ---- prep: edge decode + CSR + dis + weight splits ----
    init_kernel<<<NB, TB>>>(M);
    detect_kernel<<<(Escan + TB - 1) / TB, TB>>>((const unsigned long long*)ei, Escan, M);
    convert_kernel<<<(E + TB - 1) / TB, TB>>>(ei, E);
    partsum_kernel<<<NB, 256>>>(M);
    scanpart_kernel<<<1, 256>>>(NB);
    scanfinal_kernel<<<NB, 256>>>(M);
    fill_kernel<<<(E + TB - 1) / TB, TB>>>(E);
    wsplit_all<<<(WSPLIT_N + TB - 1) / TB, TB>>>(W1, W2, Wfc);

    // ---- layer 1: a = split(A_hat x) ; h1 = a @ W1 (stats fused) ----
    gather1_kernel<<<gatherBlocks, TB>>>(x, ahi, alo, M);
    gemm_mma<NFEAT, false, true><<<gemmGrid, TB, SMEM>>>(ahi, alo, (bf16*)p_w1h, (bf16*)p_w1l, h, M, nullptr);
    bn_finalize<<<1, HID>>>(g1, be1, M);

    // ---- layer 2: z = dis*bn1(h1) ; a = split(gather z) ; h2 = a @ W2 ----
    scale_kernel<<<(M * HID / 4 + TB - 1) / TB, TB>>>(h, z, M * HID / 4);
    gather2_kernel<<<gatherBlocks, TB>>>(z, ahi, alo, M);
    gemm_mma<HID, false, true><<<gemmGrid, TB, SMEM>>>(ahi, alo, (bf16*)p_w2h, (bf16*)p_w2l, h, M, nullptr);
    bn_finalize<<<1, HID>>>(g2, be2, M);

    // ---- FC: out = bn2(h2) @ Wfc + bfc ----
    split_affine_kernel<<<(M * HID / 4 + TB - 1) / TB, TB>>>(h, ahi, alo, M * HID / 4);
    gemm_mma<HID, true, false><<<gemmGrid, TB, SMEM>>>(ahi, alo, (bf16*)p_wfh, (bf16*)p_wfl, out, M, bfc);
}

// round 10
// speedup vs baseline: 4.3081x; 1.0096x over previous
#include <cuda_runtime.h>
#include <cuda_bf16.h>
#include <cstdint>

#define N_NODES_MAX 50000
#define N_EDGES_MAX 800000
#define NFEAT 128
#define HID 256
#define BN_EPS 1e-5f

typedef __nv_bfloat16 bf16;

// ---------------- scratch (static __device__, no allocation) ----------------
__device__ float  g_h  [(size_t)N_NODES_MAX * HID];
__device__ bf16   g_ahi[(size_t)N_NODES_MAX * HID];
__device__ bf16   g_alo[(size_t)N_NODES_MAX * HID];
__device__ bf16   g_w1h[HID * NFEAT], g_w1l[HID * NFEAT];     // [N][K] transposed
__device__ bf16   g_w2h[HID * HID],   g_w2l[HID * HID];
__device__ bf16   g_wfh[HID * HID],   g_wfl[HID * HID];
__device__ float  g_dis[N_NODES_MAX];
__device__ int    g_deg[N_NODES_MAX];
__device__ int    g_rowoff[N_NODES_MAX];
__device__ int    g_cursor[N_NODES_MAX];
__device__ int    g_src[N_EDGES_MAX];
__device__ int    g_dst[N_EDGES_MAX];
__device__ int    g_csr[N_EDGES_MAX];
__device__ int    g_part[256];
__device__ int    g_partscan[256];
__device__ int    g_is32;        // statically 0; set-only (monotone, deterministic)
__device__ double g_sum[HID];
__device__ double g_sumsq[HID];
__device__ float  g_bns[HID];
__device__ float  g_bnt[HID];

// ---------------- prep: init + dtype probe fused ----------------
// Sample-scan first <=8192 64-bit words: genuine int64 indices < M;
// packed int32 pairs >= 2^32 almost surely. Ballot -> <=1 store/warp.
__global__ void init_kernel(const unsigned long long* __restrict__ p,
                            int Escan, int n, int M) {
    int i = blockIdx.x * blockDim.x + threadIdx.x;
    if (i < n) g_deg[i] = 0;
    if (i < HID) { g_sum[i] = 0.0; g_sumsq[i] = 0.0; }
    bool bad = (i < Escan) && (p[i] >= (unsigned long long)M);
    unsigned b = __ballot_sync(~0u, bad);
    if (b && (threadIdx.x & 31) == 0) g_is32 = 1;
}

__global__ void convert_kernel(const void* __restrict__ ei, int E) {
    int e = blockIdx.x * blockDim.x + threadIdx.x;
    if (e >= E) return;
    int s, d;
    if (g_is32) {
        const int* p = (const int*)ei;
        s = p[e]; d = p[E + e];
    } else {
        const long long* p = (const long long*)ei;
        s = (int)p[e]; d = (int)p[(size_t)E + e];
    }
    g_src[e] = s;
    g_dst[e] = d;
    atomicAdd(&g_deg[d], 1);
}

__global__ void __launch_bounds__(256)
partsum_kernel(int M) {
    __shared__ int sh[8];
    const int tid = threadIdx.x;
    int i = blockIdx.x * 256 + tid;
    int v = (i < M) ? g_deg[i] : 0;
    #pragma unroll
    for (int o = 16; o > 0; o >>= 1) v += __shfl_down_sync(~0u, v, o);
    if ((tid & 31) == 0) sh[tid >> 5] = v;
    __syncthreads();
    if (tid < 8) {
        int w = sh[tid];
        #pragma unroll
        for (int o = 4; o > 0; o >>= 1) w += __shfl_down_sync(0xffu, w, o);
        if (tid == 0) g_part[blockIdx.x] = w;
    }
}

__global__ void __launch_bounds__(256)
scanpart_kernel(int NB) {
    __shared__ int sh[256];
    const int t = threadIdx.x;
    sh[t] = (t < NB) ? g_part[t] : 0;
    __syncthreads();
    for (int off = 1; off < 256; off <<= 1) {
        int v = (t >= off) ? sh[t - off] : 0;
        __syncthreads();
        sh[t] += v;
        __syncthreads();
    }
    if (t < NB) g_partscan[t] = (t == 0) ? 0 : sh[t - 1];
}

__global__ void __launch_bounds__(256)
scanfinal_kernel(int M) {
    __shared__ int sh[8];
    const int tid = threadIdx.x;
    int i = blockIdx.x * 256 + tid;
    int d = (i < M) ? g_deg[i] : 0;
    int v = d;
    #pragma unroll
    for (int o = 1; o < 32; o <<= 1) {
        int u = __shfl_up_sync(~0u, v, o);
        if ((tid & 31) >= o) v += u;
    }
    if ((tid & 31) == 31) sh[tid >> 5] = v;
    __syncthreads();
    if (tid < 8) {
        int w = sh[tid];
        #pragma unroll
        for (int o = 1; o < 8; o <<= 1) {
            int u = __shfl_up_sync(0xffu, w, o);
            if (tid >= o) w += u;
        }
        sh[tid] = w;
    }
    __syncthreads();
    int warpBase = (tid >= 32) ? sh[(tid >> 5) - 1] : 0;
    int excl = g_partscan[blockIdx.x] + warpBase + v - d;
    if (i < M) {
        g_rowoff[i] = excl;
        g_cursor[i] = excl;
        g_dis[i] = rsqrtf((float)(d + 1));
    }
}

__global__ void fill_kernel(int E) {
    int e = blockIdx.x * blockDim.x + threadIdx.x;
    if (e >= E) return;
    int d = g_dst[e];
    int pos = atomicAdd(&g_cursor[d], 1);
    g_csr[pos] = g_src[e];
}

// ---------------- all weight splits in ONE kernel (transposed) ----------------
__global__ void wsplit_all(const float* __restrict__ W1,
                           const float* __restrict__ W2,
                           const float* __restrict__ Wfc) {
    int idx = blockIdx.x * blockDim.x + threadIdx.x;
    const float* W; bf16 *hip, *lop; int K; int off;
    const int S1 = NFEAT * HID, S2 = S1 + HID * HID, S3 = S2 + HID * HID;
    if (idx < S1)      { W = W1;  hip = g_w1h; lop = g_w1l; K = NFEAT; off = idx; }
    else if (idx < S2) { W = W2;  hip = g_w2h; lop = g_w2l; K = HID;   off = idx - S1; }
    else if (idx < S3) { W = Wfc; hip = g_wfh; lop = g_wfl; K = HID;   off = idx - S2; }
    else return;
    int k = off >> 8;
    int n = off & 255;
    float v = W[off];
    bf16 h = __float2bfloat16(v);
    bf16 l = __float2bfloat16(v - __bfloat162float(h));
    hip[(size_t)n * K + k] = h;
    lop[(size_t)n * K + k] = l;
}

// ---------------- split helpers ----------------
__device__ __forceinline__ uint32_t pack2(float a, float b) {
    __nv_bfloat162 t = __floats2bfloat162_rn(a, b);
    return *(uint32_t*)&t;
}

__device__ __forceinline__ void split4(const float4 v, uint2& H, uint2& L) {
    float hx = __bfloat162float(__float2bfloat16(v.x));
    float hy = __bfloat162float(__float2bfloat16(v.y));
    float hz = __bfloat162float(__float2bfloat16(v.z));
    float hw = __bfloat162float(__float2bfloat16(v.w));
    H.x = pack2(v.x, v.y); H.y = pack2(v.z, v.w);
    L.x = pack2(v.x - hx, v.y - hy); L.y = pack2(v.z - hz, v.w - hw);
}

__global__ void __launch_bounds__(256)
split_affine_kernel(const float* __restrict__ in, bf16* __restrict__ hi,
                    bf16* __restrict__ lo, int n4) {
    int i = blockIdx.x * blockDim.x + threadIdx.x;
    if (i >= n4) return;
    float4 v = __ldg((const float4*)in + i);
    int c = (i * 4) & 255;
    float4 s = *(const float4*)(g_bns + c);
    float4 t = *(const float4*)(g_bnt + c);
    v.x = fmaf(v.x, s.x, t.x); v.y = fmaf(v.y, s.y, t.y);
    v.z = fmaf(v.z, s.z, t.z); v.w = fmaf(v.w, s.w, t.w);
    uint2 H, L;
    split4(v, H, L);
    *((uint2*)hi + i) = H;
    *((uint2*)lo + i) = L;
}

// ---------------- tensor-core GEMM with fused BN stats ----------------
__device__ __forceinline__ void mma16816(float* c, const uint32_t* a,
                                         const uint32_t* b) {
    asm volatile(
        "mma.sync.aligned.m16n8k16.row.col.f32.bf16.bf16.f32 "
        "{%0,%1,%2,%3}, {%4,%5,%6,%7}, {%8,%9}, {%0,%1,%2,%3};"
        : "+f"(c[0]), "+f"(c[1]), "+f"(c[2]), "+f"(c[3])
        : "r"(a[0]), "r"(a[1]), "r"(a[2]), "r"(a[3]), "r"(b[0]), "r"(b[1]));
}

__device__ __forceinline__ void cpa16(void* s, const void* g) {
    uint32_t sa = (uint32_t)__cvta_generic_to_shared(s);
    asm volatile("cp.async.cg.shared.global [%0], [%1], 16;" :: "r"(sa), "l"(g));
}

#define SM_STAGE 36864
#define SM_AL    6144
#define SM_BH    12288
#define SM_BL    24576

template<int K, bool ADD_BIAS, bool STATS>
__global__ void __launch_bounds__(256)
gemm_mma(const bf16* __restrict__ Ahi, const bf16* __restrict__ Alo,
         const bf16* __restrict__ Bhi, const bf16* __restrict__ Blo,
         float* __restrict__ C, int M, const float* __restrict__ bias)
{
    extern __shared__ char smbuf[];
    __shared__ float s_sum[HID], s_sq[HID];
    constexpr int NK = K / 16;
    const int tid = threadIdx.x;
    const int l   = tid & 31;
    const int wid = tid >> 5;
    const int wm  = (wid & 1) * 64;
    const int wn  = (wid >> 1) * 64;
    const int rowBase = blockIdx.x * 128;

    const int arow  = tid >> 1;
    const int ahalf = tid & 1;
    const int gar   = min(rowBase + arow, M - 1);
    const size_t aoff = (size_t)gar * K + ahalf * 8;
    const int asm_off = arow * 48 + ahalf * 16;

    if (STATS) { s_sum[tid] = 0.f; s_sq[tid] = 0.f; }

    float acc[4][8][4] = {};

    auto issue = [&](int kt, int buf) {
        char* st = smbuf + buf * SM_STAGE;
        int ko = kt * 16;
        cpa16(st + asm_off,         Ahi + aoff + ko);
        cpa16(st + SM_AL + asm_off, Alo + aoff + ko);
        #pragma unroll
        for (int q = 0; q < 2; q++) {
            int slot = tid + q * 256;
            int n = slot >> 1, hh = slot & 1;
            size_t boff = (size_t)n * K + ko + hh * 8;
            int so = n * 48 + hh * 16;
            cpa16(st + SM_BH + so, Bhi + boff);
            cpa16(st + SM_BL + so, Blo + boff);
        }
    };

    issue(0, 0);
    asm volatile("cp.async.commit_group;");

    const int kq = l & 3;
    const int rl = l >> 2;

    for (int kt = 0; kt < NK; kt++) {
        const int buf = kt & 1;
        if (kt + 1 < NK) {
            issue(kt + 1, buf ^ 1);
            asm volatile("cp.async.commit_group;");
            asm volatile("cp.async.wait_group 1;");
        } else {
            asm volatile("cp.async.wait_group 0;");
        }
        __syncthreads();

        const bf16* Ah = (const bf16*)(smbuf + buf * SM_STAGE);
        const bf16* Al = (const bf16*)(smbuf + buf * SM_STAGE + SM_AL);
        const bf16* Bh = (const bf16*)(smbuf + buf * SM_STAGE + SM_BH);
        const bf16* Bl = (const bf16*)(smbuf + buf * SM_STAGE + SM_BL);

        uint32_t ah[4][4], al[4][4];
        #pragma unroll
        for (int mi = 0; mi < 4; mi++) {
            int r = wm + mi * 16 + rl;
            ah[mi][0] = *(const uint32_t*)(Ah + r * 24 + kq * 2);
            ah[mi][1] = *(const uint32_t*)(Ah + (r + 8) * 24 + kq * 2);
            ah[mi][2] = *(const uint32_t*)(Ah + r * 24 + kq * 2 + 8);
            ah[mi][3] = *(const uint32_t*)(Ah + (r + 8) * 24 + kq * 2 + 8);
            al[mi][0] = *(const uint32_t*)(Al + r * 24 + kq * 2);
            al[mi][1] = *(const uint32_t*)(Al + (r + 8) * 24 + kq * 2);
            al[mi][2] = *(const uint32_t*)(Al + r * 24 + kq * 2 + 8);
            al[mi][3] = *(const uint32_t*)(Al + (r + 8) * 24 + kq * 2 + 8);
        }

        #pragma unroll
        for (int nh = 0; nh < 2; nh++) {
            uint32_t bh[4][2], bl[4][2];
            #pragma unroll
            for (int nj = 0; nj < 4; nj++) {
                int n = wn + nh * 32 + nj * 8 + rl;
                bh[nj][0] = *(const uint32_t*)(Bh + n * 24 + kq * 2);
                bh[nj][1] = *(const uint32_t*)(Bh + n * 24 + kq * 2 + 8);
                bl[nj][0] = *(const uint32_t*)(Bl + n * 24 + kq * 2);
                bl[nj][1] = *(const uint32_t*)(Bl + n * 24 + kq * 2 + 8);
            }
            #pragma unroll
            for (int mi = 0; mi < 4; mi++)
                #pragma unroll
                for (int nj = 0; nj < 4; nj++) {
                    float* c = acc[mi][nh * 4 + nj];
                    mma16816(c, ah[mi], bh[nj]);
                    mma16816(c, ah[mi], bl[nj]);
                    mma16816(c, al[mi], bh[nj]);
                }
        }
        __syncthreads();
    }

    // ---- epilogue: store + optional fused column stats ----
    #pragma unroll
    for (int nn = 0; nn < 8; nn++) {
        int col = wn + nn * 8 + kq * 2;
        float2 bb = make_float2(0.f, 0.f);
        if (ADD_BIAS) bb = *(const float2*)(bias + col);
        #pragma unroll
        for (int mi = 0; mi < 4; mi++) {
            int r = rowBase + wm + mi * 16 + rl;
            if (r < M) {
                float2 v = make_float2(acc[mi][nn][0] + bb.x,
                                       acc[mi][nn][1] + bb.y);
                *(float2*)(C + (size_t)r * HID + col) = v;
            }
            if (r + 8 < M) {
                float2 v = make_float2(acc[mi][nn][2] + bb.x,
                                       acc[mi][nn][3] + bb.y);
                *(float2*)(C + (size_t)(r + 8) * HID + col) = v;
            }
        }
    }

    if (STATS) {
        #pragma unroll
        for (int nn = 0; nn < 8; nn++) {
            float s0 = 0.f, q0 = 0.f, s1 = 0.f, q1 = 0.f;
            #pragma unroll
            for (int mi = 0; mi < 4; mi++) {
                int r = rowBase + wm + mi * 16 + rl;
                if (r < M) {
                    float v0 = acc[mi][nn][0], v1 = acc[mi][nn][1];
                    s0 += v0; q0 += v0 * v0; s1 += v1; q1 += v1 * v1;
                }
                if (r + 8 < M) {
                    float v0 = acc[mi][nn][2], v1 = acc[mi][nn][3];
                    s0 += v0; q0 += v0 * v0; s1 += v1; q1 += v1 * v1;
                }
            }
            #pragma unroll
            for (int o = 16; o >= 4; o >>= 1) {
                s0 += __shfl_down_sync(~0u, s0, o);
                q0 += __shfl_down_sync(~0u, q0, o);
                s1 += __shfl_down_sync(~0u, s1, o);
                q1 += __shfl_down_sync(~0u, q1, o);
            }
            if (l < 4) {
                int col = wn + nn * 8 + kq * 2;
                atomicAdd(&s_sum[col], s0);     atomicAdd(&s_sq[col], q0);
                atomicAdd(&s_sum[col + 1], s1); atomicAdd(&s_sq[col + 1], q1);
            }
        }
        __syncthreads();
        atomicAdd(&g_sum[tid],   (double)s_sum[tid]);
        atomicAdd(&g_sumsq[tid], (double)s_sq[tid]);
    }
}

// ---------------- gather kernels (split fused into epilogue) ----------------
// gather1: width 128, input x. out = split( dn*(dn*x_i + sum_j dj*x_j) )
__global__ void __launch_bounds__(256)
gather1_kernel(const float* __restrict__ x, bf16* __restrict__ hi,
               bf16* __restrict__ lo, int M)
{
    const int lane = threadIdx.x & 31;
    int gwarp = (blockIdx.x * blockDim.x + threadIdx.x) >> 5;
    int nwarp = (gridDim.x * blockDim.x) >> 5;

    for (int n = gwarp; n < M; n += nwarp) {
        const float dn = g_dis[n];
        float4 a = __ldg((const float4*)(x + (size_t)n * NFEAT) + lane);
        a.x *= dn; a.y *= dn; a.z *= dn; a.w *= dn;
        const int roff = g_rowoff[n];
        const int dc = g_deg[n];
        int j = 0;
        for (; j + 1 < dc; j += 2) {
            int s0 = __ldg(g_csr + roff + j);
            int s1 = __ldg(g_csr + roff + j + 1);
            float d0 = g_dis[s0], d1 = g_dis[s1];
            float4 b = __ldg((const float4*)(x + (size_t)s0 * NFEAT) + lane);
            float4 c = __ldg((const float4*)(x + (size_t)s1 * NFEAT) + lane);
            a.x += b.x * d0 + c.x * d1; a.y += b.y * d0 + c.y * d1;
            a.z += b.z * d0 + c.z * d1; a.w += b.w * d0 + c.w * d1;
        }
        if (j < dc) {
            int s0 = __ldg(g_csr + roff + j);
            float d0 = g_dis[s0];
            float4 b = __ldg((const float4*)(x + (size_t)s0 * NFEAT) + lane);
            a.x += b.x * d0; a.y += b.y * d0; a.z += b.z * d0; a.w += b.w * d0;
        }
        a.x *= dn; a.y *= dn; a.z *= dn; a.w *= dn;
        uint2 H, L;
        split4(a, H, L);
        *((uint2*)(hi + (size_t)n * NFEAT) + lane) = H;
        *((uint2*)(lo + (size_t)n * NFEAT) + lane) = L;
    }
}

// gather2: width 256, input RAW h. BN affine commuted past aggregation:
//   a2 = u*s + r*t, where u = dn*(dn*h_i + sum_j dj*h_j),
//                         r = dn*(dn + sum_j dj)    (= (A_hat 1)_i )
__global__ void __launch_bounds__(256)
gather2_kernel(const float* __restrict__ h, bf16* __restrict__ hi,
               bf16* __restrict__ lo, int M)
{
    const int lane = threadIdx.x & 31;
    int gwarp = (blockIdx.x * blockDim.x + threadIdx.x) >> 5;
    int nwarp = (gridDim.x * blockDim.x) >> 5;

    const float4 s0 = *(const float4*)(g_bns + lane * 4);
    const float4 t0 = *(const float4*)(g_bnt + lane * 4);
    const float4 s1 = *(const float4*)(g_bns + 128 + lane * 4);
    const float4 t1 = *(const float4*)(g_bnt + 128 + lane * 4);

    for (int n = gwarp; n < M; n += nwarp) {
        const float dn = g_dis[n];
        const float4* sp = (const float4*)(h + (size_t)n * HID);
        float4 a0 = __ldg(sp + lane);
        float4 a1 = __ldg(sp + lane + 32);
        a0.x *= dn; a0.y *= dn; a0.z *= dn; a0.w *= dn;
        a1.x *= dn; a1.y *= dn; a1.z *= dn; a1.w *= dn;
        float w = dn;

        const int roff = g_rowoff[n];
        const int dc = g_deg[n];
        int j = 0;
        for (; j + 1 < dc; j += 2) {
            int e0 = __ldg(g_csr + roff + j);
            int e1 = __ldg(g_csr + roff + j + 1);
            float d0 = g_dis[e0], d1 = g_dis[e1];
            const float4* p0 = (const float4*)(h + (size_t)e0 * HID);
            const float4* p1 = (const float4*)(h + (size_t)e1 * HID);
            float4 b0 = __ldg(p0 + lane);
            float4 b1 = __ldg(p0 + lane + 32);
            float4 c0 = __ldg(p1 + lane);
            float4 c1 = __ldg(p1 + lane + 32);
            a0.x += b0.x * d0 + c0.x * d1; a0.y += b0.y * d0 + c0.y * d1;
            a0.z += b0.z * d0 + c0.z * d1; a0.w += b0.w * d0 + c0.w * d1;
            a1.x += b1.x * d0 + c1.x * d1; a1.y += b1.y * d0 + c1.y * d1;
            a1.z += b1.z * d0 + c1.z * d1; a1.w += b1.w * d0 + c1.w * d1;
            w += d0 + d1;
        }
        if (j < dc) {
            int e0 = __ldg(g_csr + roff + j);
            float d0 = g_dis[e0];
            const float4* p0 = (const float4*)(h + (size_t)e0 * HID);
            float4 b0 = __ldg(p0 + lane);
            float4 b1 = __ldg(p0 + lane + 32);
            a0.x += b0.x * d0; a0.y += b0.y * d0;
            a0.z += b0.z * d0; a0.w += b0.w * d0;
            a1.x += b1.x * d0; a1.y += b1.y * d0;
            a1.z += b1.z * d0; a1.w += b1.w * d0;
            w += d0;
        }

        const float r = dn * w;
        float4 v0, v1;
        v0.x = fmaf(dn * a0.x, s0.x, r * t0.x);
        v0.y = fmaf(dn * a0.y, s0.y, r * t0.y);
        v0.z = fmaf(dn * a0.z, s0.z, r * t0.z);
        v0.w = fmaf(dn * a0.w, s0.w, r * t0.w);
        v1.x = fmaf(dn * a1.x, s1.x, r * t1.x);
        v1.y = fmaf(dn * a1.y, s1.y, r * t1.y);
        v1.z = fmaf(dn * a1.z, s1.z, r * t1.z);
        v1.w = fmaf(dn * a1.w, s1.w, r * t1.w);

        uint2 H0, L0, H1, L1;
        split4(v0, H0, L0);
        split4(v1, H1, L1);
        *((uint2*)(hi + (size_t)n * HID) + lane) = H0;
        *((uint2*)(hi + (size_t)n * HID) + lane + 32) = H1;
        *((uint2*)(lo + (size_t)n * HID) + lane) = L0;
        *((uint2*)(lo + (size_t)n * HID) + lane + 32) = L1;
    }
}

__global__ void bn_finalize(const float* __restrict__ gamma,
                            const float* __restrict__ beta, int M)
{
    int c = threadIdx.x;
    double m   = g_sum[c] / (double)M;
    double var = g_sumsq[c] / (double)M - m * m;
    float sc = gamma[c] * rsqrtf((float)var + BN_EPS);
    g_bns[c] = sc;
    g_bnt[c] = beta[c] - (float)m * sc;
    g_sum[c] = 0.0; g_sumsq[c] = 0.0;
}

// ---------------- launch ----------------
extern "C" void kernel_launch(void* const* d_in, const int* in_sizes, int n_in,
                              void* d_out, int out_size)
{
    const float* x   = (const float*)d_in[0];
    const void*  ei  = d_in[1];
    const float* W1  = (const float*)d_in[2];
    const float* g1  = (const float*)d_in[4];
    const float* be1 = (const float*)d_in[5];
    const float* W2  = (const float*)d_in[6];
    const float* g2  = (const float*)d_in[8];
    const float* be2 = (const float*)d_in[9];
    const float* Wfc = (const float*)d_in[10];
    const float* bfc = (const float*)d_in[11];
    float* out = (float*)d_out;

    const int M = in_sizes[0] / NFEAT;   // 50000
    const int E = in_sizes[1] / 2;       // 800000

    void *p_h, *p_ahi, *p_alo;
    void *p_w1h, *p_w1l, *p_w2h, *p_w2l, *p_wfh, *p_wfl;
    cudaGetSymbolAddress(&p_h, g_h);
    cudaGetSymbolAddress(&p_ahi, g_ahi);
    cudaGetSymbolAddress(&p_alo, g_alo);
    cudaGetSymbolAddress(&p_w1h, g_w1h);
    cudaGetSymbolAddress(&p_w1l, g_w1l);
    cudaGetSymbolAddress(&p_w2h, g_w2h);
    cudaGetSymbolAddress(&p_w2l, g_w2l);
    cudaGetSymbolAddress(&p_wfh, g_wfh);
    cudaGetSymbolAddress(&p_wfl, g_wfl);
    float* h = (float*)p_h;
    bf16 *ahi = (bf16*)p_ahi, *alo = (bf16*)p_alo;

    const int TB = 256;
    const int NB = (M + 255) / 256;
    const int gemmGrid = (M + 127) / 128;
    const int gatherBlocks = 592;
    const int SMEM = 2 * SM_STAGE;
    const int Escan = (E < 8192) ? E : 8192;
    const int WSPLIT_N = NFEAT * HID + 2 * HID * HID;

    cudaFuncSetAttribute(gemm_mma<NFEAT, false, true>,
                         cudaFuncAttributeMaxDynamicSharedMemorySize, SMEM);
    cudaFuncSetAttribute(gemm_mma<HID, false, true>,
                         cudaFuncAttributeMaxDynamicSharedMemorySize, SMEM);
    cudaFuncSetAttribute(gemm_mma<HID, true, false>,
                         cudaFuncAttributeMaxDynamicSharedMemorySize, SMEM);

    // ---- prep: (init + dtype probe) + edge decode + CSR + dis + wsplit ----
    init_kernel<<<NB, TB>>>((const unsigned long long*)ei, Escan, M, M);
    convert_kernel<<<(E + TB - 1) / TB, TB>>>(ei, E);
    partsum_kernel<<<NB, 256>>>(M);
    scanpart_kernel<<<1, 256>>>(NB);
    scanfinal_kernel<<<NB, 256>>>(M);
    fill_kernel<<<(E + TB - 1) / TB, TB>>>(E);
    wsplit_all<<<(WSPLIT_N + TB - 1) / TB, TB>>>(W1, W2, Wfc);

    // ---- layer 1: a = split(A_hat x) ; h1 = a @ W1 (stats fused) ----
    gather1_kernel<<<gatherBlocks, TB>>>(x, ahi, alo, M);
    gemm_mma<NFEAT, false, true><<<gemmGrid, TB, SMEM>>>(ahi, alo, (bf16*)p_w1h, (bf16*)p_w1l, h, M, nullptr);
    bn_finalize<<<1, HID>>>(g1, be1, M);

    // ---- layer 2: a = split(A_hat bn1(h1)) via affine-commute ; h2 = a @ W2 ----
    gather2_kernel<<<gatherBlocks, TB>>>(h, ahi, alo, M);
    gemm_mma<HID, false, true><<<gemmGrid, TB, SMEM>>>(ahi, alo, (bf16*)p_w2h, (bf16*)p_w2l, h, M, nullptr);
    bn_finalize<<<1, HID>>>(g2, be2, M);

    // ---- FC: out = bn2(h2) @ Wfc + bfc ----
    split_affine_kernel<<<(M * HID / 4 + TB - 1) / TB, TB>>>(h, ahi, alo, M * HID / 4);
    gemm_mma<HID, true, false><<<gemmGrid, TB, SMEM>>>(ahi, alo, (bf16*)p_wfh, (bf16*)p_wfl, out, M, bfc);
}